// round 1
// baseline (speedup 1.0000x reference)
#include <cuda_runtime.h>
#include <math.h>

// Problem constants
constexpr int B_  = 2;
constexpr int T_  = 2048;
constexpr int D_  = 1024;
constexpr int H_  = 16;
constexpr int HD_ = 64;
constexpr int BT_ = B_ * T_;     // 4096
constexpr int D3_ = 3 * D_;      // 3072

// Scratch (allocation-free rule: __device__ globals)
__device__ float g_qkv[BT_ * D3_];            // (B*T, 3D)
__device__ float g_q[B_ * H_ * T_ * HD_];     // (B,H,T,HD)
__device__ float g_k[B_ * H_ * T_ * HD_];
__device__ float g_v[B_ * H_ * T_ * HD_];
__device__ float g_attn[BT_ * D_];            // (B*T, D)

// ---------------------------------------------------------------------------
// Polynomial exp (avoids MUFU bottleneck: 268M exps would be ~2ms on MUFU).
// Valid for x <= 0 (softmax use). ~1e-7 rel err.
// ---------------------------------------------------------------------------
__device__ __forceinline__ float fast_exp(float x) {
    x = fmaxf(x, -80.0f);
    float y = x * 1.4426950408889634f;   // x * log2(e)
    float n = rintf(y);
    float f = y - n;                      // [-0.5, 0.5]
    float g = f * 0.6931471805599453f;    // back to natural-log domain
    float p = 1.0f / 720.0f;
    p = fmaf(p, g, 1.0f / 120.0f);
    p = fmaf(p, g, 1.0f / 24.0f);
    p = fmaf(p, g, 1.0f / 6.0f);
    p = fmaf(p, g, 0.5f);
    p = fmaf(p, g, 1.0f);
    p = fmaf(p, g, 1.0f);
    int e = (int)n;                       // e in [-116, 0] after clamp
    return p * __int_as_float((e + 127) << 23);
}

// ---------------------------------------------------------------------------
// Tiled fp32 SGEMM: C[M,N] = A[M,K] @ B[K,N] + bias[N]
// BM=BN=128, BK=8, 256 threads, 8x8 per thread. Shapes are exact multiples.
// ---------------------------------------------------------------------------
__global__ void sgemm_bias_kernel(const float* __restrict__ A,
                                  const float* __restrict__ Bm,
                                  const float* __restrict__ bias,
                                  float* __restrict__ C,
                                  int M, int N, int K) {
    constexpr int BM = 128, BN = 128, BK = 8, TM = 8, TN = 8;
    __shared__ float As[BK][BM];   // transposed A tile
    __shared__ float Bs[BK][BN];

    const int tid = threadIdx.x;       // 0..255
    const int tr  = tid >> 4;          // 0..15
    const int tc  = tid & 15;          // 0..15
    const int rowBase = blockIdx.y * BM;
    const int colBase = blockIdx.x * BN;

    // A tile load mapping: 128 rows x 8 cols = 256 float4
    const int aRow = tid >> 1;
    const int aCol = (tid & 1) << 2;
    // B tile load mapping: 8 rows x 128 cols = 256 float4
    const int bRow = tid >> 5;
    const int bCol = (tid & 31) << 2;

    const float* Aptr = A + (size_t)(rowBase + aRow) * K + aCol;
    const float* Bptr = Bm + (size_t)bRow * N + colBase + bCol;

    float acc[TM][TN];
#pragma unroll
    for (int i = 0; i < TM; i++)
#pragma unroll
        for (int j = 0; j < TN; j++) acc[i][j] = 0.0f;

    for (int k0 = 0; k0 < K; k0 += BK) {
        float4 a4 = *reinterpret_cast<const float4*>(Aptr + k0);
        float4 b4 = *reinterpret_cast<const float4*>(Bptr + (size_t)k0 * N);
        As[aCol + 0][aRow] = a4.x;
        As[aCol + 1][aRow] = a4.y;
        As[aCol + 2][aRow] = a4.z;
        As[aCol + 3][aRow] = a4.w;
        *reinterpret_cast<float4*>(&Bs[bRow][bCol]) = b4;
        __syncthreads();

#pragma unroll
        for (int k = 0; k < BK; k++) {
            float ra[TM], rb[TN];
#pragma unroll
            for (int i = 0; i < TM; i++) ra[i] = As[k][tr * TM + i];
#pragma unroll
            for (int j = 0; j < TN; j++) rb[j] = Bs[k][tc * TN + j];
#pragma unroll
            for (int i = 0; i < TM; i++)
#pragma unroll
                for (int j = 0; j < TN; j++)
                    acc[i][j] = fmaf(ra[i], rb[j], acc[i][j]);
        }
        __syncthreads();
    }

#pragma unroll
    for (int i = 0; i < TM; i++) {
        int r = rowBase + tr * TM + i;
#pragma unroll
        for (int j = 0; j < TN; j += 4) {
            int c = colBase + tc * TN + j;
            float4 ov;
            ov.x = acc[i][j + 0] + bias[c + 0];
            ov.y = acc[i][j + 1] + bias[c + 1];
            ov.z = acc[i][j + 2] + bias[c + 2];
            ov.w = acc[i][j + 3] + bias[c + 3];
            *reinterpret_cast<float4*>(&C[(size_t)r * N + c]) = ov;
        }
    }
}

// ---------------------------------------------------------------------------
// Transpose qkv (B,T,3,H,HD) -> q/k/v (B,H,T,HD) with RoPE fused on q,k.
// One thread per (b,h,t,d) with d in [0,32): handles the (d, d+32) pair.
// Angle math mirrors the reference's float32 computation.
// ---------------------------------------------------------------------------
__global__ void rope_transform_kernel() {
    int idx = blockIdx.x * blockDim.x + threadIdx.x;  // [0, B*H*T*32)
    int d = idx & 31;
    int t = (idx >> 5) & (T_ - 1);
    int h = (idx >> 16) & (H_ - 1);
    int b = idx >> 20;

    const float* src = g_qkv + (size_t)(b * T_ + t) * D3_ + h * HD_;
    float expo = (float)(2 * d) * (1.0f / (float)HD_);
    float inv  = 1.0f / powf(10000.0f, expo);
    float ang  = (float)t * inv;
    float s, c;
    sincosf(ang, &s, &c);

    size_t dst = ((size_t)(b * H_ + h) * T_ + t) * HD_;
    float q1 = src[d],        q2 = src[d + 32];
    g_q[dst + d]      = q1 * c - q2 * s;
    g_q[dst + d + 32] = q2 * c + q1 * s;
    float k1 = src[D_ + d],   k2 = src[D_ + d + 32];
    g_k[dst + d]      = k1 * c - k2 * s;
    g_k[dst + d + 32] = k2 * c + k1 * s;
    g_v[dst + d]      = src[2 * D_ + d];
    g_v[dst + d + 32] = src[2 * D_ + d + 32];
}

// ---------------------------------------------------------------------------
// fp32 flash attention: 64-row Q tile per block, 64-row KV tiles, online
// softmax. 256 threads = 16x16 grid, each owns a 4x4 microtile.
// Writes output directly in (B, T, H*HD) layout for the out-projection GEMM.
// ---------------------------------------------------------------------------
__global__ void flash_attn_kernel(const unsigned char* __restrict__ mask) {
    extern __shared__ float smbuf[];
    float* Qs = smbuf;               // [64][64]  (row-major, q rows)
    float* Kt = Qs + 64 * 64;        // [64][64]  Kt[d][kcol] (transposed)
    float* Vs = Kt + 64 * 64;        // [64][64]  Vs[krow][d]
    float* Ps = Vs + 64 * 64;        // [64][65]  padded P tile
    __shared__ float mk[64];

    const int bh = blockIdx.y;
    const int b  = bh >> 4;
    const int h  = bh & 15;
    const size_t base = (size_t)bh * T_ * HD_;
    const int tid = threadIdx.x;
    const int ty  = tid >> 4;
    const int tx  = tid & 15;
    const int q0  = blockIdx.x * 64;

    // load Q tile (4096 floats = 1024 float4)
    const float4* Qg  = reinterpret_cast<const float4*>(g_q + base + (size_t)q0 * HD_);
    float4*       Qs4 = reinterpret_cast<float4*>(Qs);
    for (int i = tid; i < 1024; i += 256) Qs4[i] = Qg[i];

    float m_i[4], l_i[4], o[4][4];
#pragma unroll
    for (int i = 0; i < 4; i++) {
        m_i[i] = -1e30f;
        l_i[i] = 0.0f;
#pragma unroll
        for (int j = 0; j < 4; j++) o[i][j] = 0.0f;
    }

    for (int kt = 0; kt < T_ / 64; kt++) {
        const int k0 = kt * 64;
        // load K (transposed) and V (natural)
        for (int i = tid; i < 1024; i += 256) {
            int r  = i >> 4;           // key row 0..63
            int c4 = (i & 15) << 2;    // d 0..60
            float4 kk4 = *reinterpret_cast<const float4*>(
                g_k + base + (size_t)(k0 + r) * HD_ + c4);
            Kt[(c4 + 0) * 64 + r] = kk4.x;
            Kt[(c4 + 1) * 64 + r] = kk4.y;
            Kt[(c4 + 2) * 64 + r] = kk4.z;
            Kt[(c4 + 3) * 64 + r] = kk4.w;
            *reinterpret_cast<float4*>(Vs + r * 64 + c4) =
                *reinterpret_cast<const float4*>(g_v + base + (size_t)(k0 + r) * HD_ + c4);
        }
        if (tid < 64) mk[tid] = mask[b * T_ + k0 + tid] ? -1e30f : 0.0f;
        __syncthreads();

        // S = Q K^T (this tile): each thread 4x4
        float s[4][4];
#pragma unroll
        for (int i = 0; i < 4; i++)
#pragma unroll
            for (int j = 0; j < 4; j++) s[i][j] = 0.0f;

#pragma unroll 8
        for (int d = 0; d < 64; d++) {
            float ra[4], rb[4];
#pragma unroll
            for (int i = 0; i < 4; i++) ra[i] = Qs[(4 * ty + i) * 64 + d];
#pragma unroll
            for (int j = 0; j < 4; j++) rb[j] = Kt[d * 64 + 4 * tx + j];
#pragma unroll
            for (int i = 0; i < 4; i++)
#pragma unroll
                for (int j = 0; j < 4; j++)
                    s[i][j] = fmaf(ra[i], rb[j], s[i][j]);
        }

        // online softmax per row group
#pragma unroll
        for (int i = 0; i < 4; i++) {
            float rm = -1e30f;
#pragma unroll
            for (int j = 0; j < 4; j++) {
                s[i][j] = s[i][j] * 0.125f + mk[4 * tx + j];  // scale = HD^-0.5
                rm = fmaxf(rm, s[i][j]);
            }
#pragma unroll
            for (int off = 8; off >= 1; off >>= 1)
                rm = fmaxf(rm, __shfl_xor_sync(0xffffffffu, rm, off));
            float mn    = fmaxf(m_i[i], rm);
            float alpha = fast_exp(m_i[i] - mn);
            m_i[i] = mn;
            float rs = 0.0f;
#pragma unroll
            for (int j = 0; j < 4; j++) {
                float p = fast_exp(s[i][j] - mn);
                s[i][j] = p;
                rs += p;
            }
#pragma unroll
            for (int off = 8; off >= 1; off >>= 1)
                rs += __shfl_xor_sync(0xffffffffu, rs, off);
            l_i[i] = l_i[i] * alpha + rs;
#pragma unroll
            for (int j = 0; j < 4; j++) o[i][j] *= alpha;
#pragma unroll
            for (int j = 0; j < 4; j++)
                Ps[(4 * ty + i) * 65 + 4 * tx + j] = s[i][j];
        }
        __syncthreads();

        // O += P @ V
#pragma unroll 8
        for (int kk = 0; kk < 64; kk++) {
            float pa[4], vb[4];
#pragma unroll
            for (int i = 0; i < 4; i++) pa[i] = Ps[(4 * ty + i) * 65 + kk];
#pragma unroll
            for (int j = 0; j < 4; j++) vb[j] = Vs[kk * 64 + 4 * tx + j];
#pragma unroll
            for (int i = 0; i < 4; i++)
#pragma unroll
                for (int j = 0; j < 4; j++)
                    o[i][j] = fmaf(pa[i], vb[j], o[i][j]);
        }
        __syncthreads();
    }

    // epilogue: normalize and scatter into (B, T, D) layout
#pragma unroll
    for (int i = 0; i < 4; i++) {
        float invl = 1.0f / l_i[i];
        int t = q0 + 4 * ty + i;
        float* dst = g_attn + (size_t)(b * T_ + t) * D_ + h * HD_ + 4 * tx * 1;
        float4 ov;
        ov.x = o[i][0] * invl;
        ov.y = o[i][1] * invl;
        ov.z = o[i][2] * invl;
        ov.w = o[i][3] * invl;
        *reinterpret_cast<float4*>(dst) = ov;
    }
}

// ---------------------------------------------------------------------------
// Launch
// ---------------------------------------------------------------------------
extern "C" void kernel_launch(void* const* d_in, const int* in_sizes, int n_in,
                              void* d_out, int out_size) {
    const float* x     = (const float*)d_in[0];
    const float* W_qkv = (const float*)d_in[1];
    const float* b_qkv = (const float*)d_in[2];
    const float* W_out = (const float*)d_in[3];
    const float* b_out = (const float*)d_in[4];
    const unsigned char* pmask = (const unsigned char*)d_in[5];
    float* out = (float*)d_out;

    float* qkv_p  = nullptr;
    float* attn_p = nullptr;
    cudaGetSymbolAddress((void**)&qkv_p,  g_qkv);
    cudaGetSymbolAddress((void**)&attn_p, g_attn);

    // 1) QKV = x @ W_qkv + b_qkv        (4096 x 3072 x 1024)
    sgemm_bias_kernel<<<dim3(D3_ / 128, BT_ / 128), 256>>>(
        x, W_qkv, b_qkv, qkv_p, BT_, D3_, D_);

    // 2) transpose + RoPE -> g_q, g_k, g_v
    rope_transform_kernel<<<(B_ * H_ * T_ * 32) / 256, 256>>>();

    // 3) flash attention -> g_attn (B,T,D)
    size_t smem = (size_t)(3 * 64 * 64 + 64 * 65) * sizeof(float);  // ~65.8 KB
    cudaFuncSetAttribute(flash_attn_kernel,
                         cudaFuncAttributeMaxDynamicSharedMemorySize, (int)smem);
    flash_attn_kernel<<<dim3(T_ / 64, B_ * H_), 256, smem>>>(pmask);

    // 4) out = attn @ W_out + b_out     (4096 x 1024 x 1024)
    sgemm_bias_kernel<<<dim3(D_ / 128, BT_ / 128), 256>>>(
        attn_p, W_out, b_out, out, BT_, D_, D_);
}

// round 2
// speedup vs baseline: 1.0002x; 1.0002x over previous
#include <cuda_runtime.h>
#include <math.h>

// Problem constants
constexpr int B_  = 2;
constexpr int T_  = 2048;
constexpr int D_  = 1024;
constexpr int H_  = 16;
constexpr int HD_ = 64;
constexpr int BT_ = B_ * T_;     // 4096
constexpr int D3_ = 3 * D_;      // 3072

// Scratch (allocation-free rule: __device__ globals)
__device__ float g_qkv[BT_ * D3_];            // (B*T, 3D)
__device__ float g_q[B_ * H_ * T_ * HD_];     // (B,H,T,HD)
__device__ float g_k[B_ * H_ * T_ * HD_];
__device__ float g_v[B_ * H_ * T_ * HD_];
__device__ float g_attn[BT_ * D_];            // (B*T, D)

// ---------------------------------------------------------------------------
// Polynomial exp (avoids MUFU bottleneck: 268M exps would be ~2ms on MUFU).
// Valid for x <= 0 (softmax use). ~1e-7 rel err.
// ---------------------------------------------------------------------------
__device__ __forceinline__ float fast_exp(float x) {
    x = fmaxf(x, -80.0f);
    float y = x * 1.4426950408889634f;   // x * log2(e)
    float n = rintf(y);
    float f = y - n;                      // [-0.5, 0.5]
    float g = f * 0.6931471805599453f;    // back to natural-log domain
    float p = 1.0f / 720.0f;
    p = fmaf(p, g, 1.0f / 120.0f);
    p = fmaf(p, g, 1.0f / 24.0f);
    p = fmaf(p, g, 1.0f / 6.0f);
    p = fmaf(p, g, 0.5f);
    p = fmaf(p, g, 1.0f);
    p = fmaf(p, g, 1.0f);
    int e = (int)n;                       // e in [-116, 0] after clamp
    return p * __int_as_float((e + 127) << 23);
}

// ---------------------------------------------------------------------------
// Tiled fp32 SGEMM: C[M,N] = A[M,K] @ B[K,N] + bias[N]
// BM=BN=128, BK=8, 256 threads, 8x8 per thread. Shapes are exact multiples.
// ---------------------------------------------------------------------------
__global__ void sgemm_bias_kernel(const float* __restrict__ A,
                                  const float* __restrict__ Bm,
                                  const float* __restrict__ bias,
                                  float* __restrict__ C,
                                  int M, int N, int K) {
    constexpr int BM = 128, BN = 128, BK = 8, TM = 8, TN = 8;
    __shared__ float As[BK][BM];   // transposed A tile
    __shared__ float Bs[BK][BN];

    const int tid = threadIdx.x;       // 0..255
    const int tr  = tid >> 4;          // 0..15
    const int tc  = tid & 15;          // 0..15
    const int rowBase = blockIdx.y * BM;
    const int colBase = blockIdx.x * BN;

    // A tile load mapping: 128 rows x 8 cols = 256 float4
    const int aRow = tid >> 1;
    const int aCol = (tid & 1) << 2;
    // B tile load mapping: 8 rows x 128 cols = 256 float4
    const int bRow = tid >> 5;
    const int bCol = (tid & 31) << 2;

    const float* Aptr = A + (size_t)(rowBase + aRow) * K + aCol;
    const float* Bptr = Bm + (size_t)bRow * N + colBase + bCol;

    float acc[TM][TN];
#pragma unroll
    for (int i = 0; i < TM; i++)
#pragma unroll
        for (int j = 0; j < TN; j++) acc[i][j] = 0.0f;

    for (int k0 = 0; k0 < K; k0 += BK) {
        float4 a4 = *reinterpret_cast<const float4*>(Aptr + k0);
        float4 b4 = *reinterpret_cast<const float4*>(Bptr + (size_t)k0 * N);
        As[aCol + 0][aRow] = a4.x;
        As[aCol + 1][aRow] = a4.y;
        As[aCol + 2][aRow] = a4.z;
        As[aCol + 3][aRow] = a4.w;
        *reinterpret_cast<float4*>(&Bs[bRow][bCol]) = b4;
        __syncthreads();

#pragma unroll
        for (int k = 0; k < BK; k++) {
            float ra[TM], rb[TN];
#pragma unroll
            for (int i = 0; i < TM; i++) ra[i] = As[k][tr * TM + i];
#pragma unroll
            for (int j = 0; j < TN; j++) rb[j] = Bs[k][tc * TN + j];
#pragma unroll
            for (int i = 0; i < TM; i++)
#pragma unroll
                for (int j = 0; j < TN; j++)
                    acc[i][j] = fmaf(ra[i], rb[j], acc[i][j]);
        }
        __syncthreads();
    }

#pragma unroll
    for (int i = 0; i < TM; i++) {
        int r = rowBase + tr * TM + i;
#pragma unroll
        for (int j = 0; j < TN; j += 4) {
            int c = colBase + tc * TN + j;
            float4 ov;
            ov.x = acc[i][j + 0] + bias[c + 0];
            ov.y = acc[i][j + 1] + bias[c + 1];
            ov.z = acc[i][j + 2] + bias[c + 2];
            ov.w = acc[i][j + 3] + bias[c + 3];
            *reinterpret_cast<float4*>(&C[(size_t)r * N + c]) = ov;
        }
    }
}

// ---------------------------------------------------------------------------
// Transpose qkv (B,T,3,H,HD) -> q/k/v (B,H,T,HD) with RoPE fused on q,k.
// One thread per (b,h,t,d) with d in [0,32): handles the (d, d+32) pair.
// Angle math mirrors the reference's float32 computation.
// ---------------------------------------------------------------------------
__global__ void rope_transform_kernel() {
    int idx = blockIdx.x * blockDim.x + threadIdx.x;  // [0, B*H*T*32)
    int d = idx & 31;
    int t = (idx >> 5) & (T_ - 1);
    int h = (idx >> 16) & (H_ - 1);
    int b = idx >> 20;

    const float* src = g_qkv + (size_t)(b * T_ + t) * D3_ + h * HD_;
    float expo = (float)(2 * d) * (1.0f / (float)HD_);
    float inv  = 1.0f / powf(10000.0f, expo);
    float ang  = (float)t * inv;
    float s, c;
    sincosf(ang, &s, &c);

    size_t dst = ((size_t)(b * H_ + h) * T_ + t) * HD_;
    float q1 = src[d],        q2 = src[d + 32];
    g_q[dst + d]      = q1 * c - q2 * s;
    g_q[dst + d + 32] = q2 * c + q1 * s;
    float k1 = src[D_ + d],   k2 = src[D_ + d + 32];
    g_k[dst + d]      = k1 * c - k2 * s;
    g_k[dst + d + 32] = k2 * c + k1 * s;
    g_v[dst + d]      = src[2 * D_ + d];
    g_v[dst + d + 32] = src[2 * D_ + d + 32];
}

// ---------------------------------------------------------------------------
// fp32 flash attention: 64-row Q tile per block, 64-row KV tiles, online
// softmax. 256 threads = 16x16 grid, each owns a 4x4 microtile.
// Writes output directly in (B, T, H*HD) layout for the out-projection GEMM.
// ---------------------------------------------------------------------------
__global__ void flash_attn_kernel(const unsigned char* __restrict__ mask) {
    extern __shared__ float smbuf[];
    float* Qs = smbuf;               // [64][64]  (row-major, q rows)
    float* Kt = Qs + 64 * 64;        // [64][64]  Kt[d][kcol] (transposed)
    float* Vs = Kt + 64 * 64;        // [64][64]  Vs[krow][d]
    float* Ps = Vs + 64 * 64;        // [64][65]  padded P tile
    __shared__ float mk[64];

    const int bh = blockIdx.y;
    const int b  = bh >> 4;
    const int h  = bh & 15;
    const size_t base = (size_t)bh * T_ * HD_;
    const int tid = threadIdx.x;
    const int ty  = tid >> 4;
    const int tx  = tid & 15;
    const int q0  = blockIdx.x * 64;

    // load Q tile (4096 floats = 1024 float4)
    const float4* Qg  = reinterpret_cast<const float4*>(g_q + base + (size_t)q0 * HD_);
    float4*       Qs4 = reinterpret_cast<float4*>(Qs);
    for (int i = tid; i < 1024; i += 256) Qs4[i] = Qg[i];

    float m_i[4], l_i[4], o[4][4];
#pragma unroll
    for (int i = 0; i < 4; i++) {
        m_i[i] = -1e30f;
        l_i[i] = 0.0f;
#pragma unroll
        for (int j = 0; j < 4; j++) o[i][j] = 0.0f;
    }

    for (int kt = 0; kt < T_ / 64; kt++) {
        const int k0 = kt * 64;
        // load K (transposed) and V (natural)
        for (int i = tid; i < 1024; i += 256) {
            int r  = i >> 4;           // key row 0..63
            int c4 = (i & 15) << 2;    // d 0..60
            float4 kk4 = *reinterpret_cast<const float4*>(
                g_k + base + (size_t)(k0 + r) * HD_ + c4);
            Kt[(c4 + 0) * 64 + r] = kk4.x;
            Kt[(c4 + 1) * 64 + r] = kk4.y;
            Kt[(c4 + 2) * 64 + r] = kk4.z;
            Kt[(c4 + 3) * 64 + r] = kk4.w;
            *reinterpret_cast<float4*>(Vs + r * 64 + c4) =
                *reinterpret_cast<const float4*>(g_v + base + (size_t)(k0 + r) * HD_ + c4);
        }
        if (tid < 64) mk[tid] = mask[b * T_ + k0 + tid] ? -1e30f : 0.0f;
        __syncthreads();

        // S = Q K^T (this tile): each thread 4x4
        float s[4][4];
#pragma unroll
        for (int i = 0; i < 4; i++)
#pragma unroll
            for (int j = 0; j < 4; j++) s[i][j] = 0.0f;

#pragma unroll 8
        for (int d = 0; d < 64; d++) {
            float ra[4], rb[4];
#pragma unroll
            for (int i = 0; i < 4; i++) ra[i] = Qs[(4 * ty + i) * 64 + d];
#pragma unroll
            for (int j = 0; j < 4; j++) rb[j] = Kt[d * 64 + 4 * tx + j];
#pragma unroll
            for (int i = 0; i < 4; i++)
#pragma unroll
                for (int j = 0; j < 4; j++)
                    s[i][j] = fmaf(ra[i], rb[j], s[i][j]);
        }

        // online softmax per row group
#pragma unroll
        for (int i = 0; i < 4; i++) {
            float rm = -1e30f;
#pragma unroll
            for (int j = 0; j < 4; j++) {
                s[i][j] = s[i][j] * 0.125f + mk[4 * tx + j];  // scale = HD^-0.5
                rm = fmaxf(rm, s[i][j]);
            }
#pragma unroll
            for (int off = 8; off >= 1; off >>= 1)
                rm = fmaxf(rm, __shfl_xor_sync(0xffffffffu, rm, off));
            float mn    = fmaxf(m_i[i], rm);
            float alpha = fast_exp(m_i[i] - mn);
            m_i[i] = mn;
            float rs = 0.0f;
#pragma unroll
            for (int j = 0; j < 4; j++) {
                float p = fast_exp(s[i][j] - mn);
                s[i][j] = p;
                rs += p;
            }
#pragma unroll
            for (int off = 8; off >= 1; off >>= 1)
                rs += __shfl_xor_sync(0xffffffffu, rs, off);
            l_i[i] = l_i[i] * alpha + rs;
#pragma unroll
            for (int j = 0; j < 4; j++) o[i][j] *= alpha;
#pragma unroll
            for (int j = 0; j < 4; j++)
                Ps[(4 * ty + i) * 65 + 4 * tx + j] = s[i][j];
        }
        __syncthreads();

        // O += P @ V
#pragma unroll 8
        for (int kk = 0; kk < 64; kk++) {
            float pa[4], vb[4];
#pragma unroll
            for (int i = 0; i < 4; i++) pa[i] = Ps[(4 * ty + i) * 65 + kk];
#pragma unroll
            for (int j = 0; j < 4; j++) vb[j] = Vs[kk * 64 + 4 * tx + j];
#pragma unroll
            for (int i = 0; i < 4; i++)
#pragma unroll
                for (int j = 0; j < 4; j++)
                    o[i][j] = fmaf(pa[i], vb[j], o[i][j]);
        }
        __syncthreads();
    }

    // epilogue: normalize and scatter into (B, T, D) layout
#pragma unroll
    for (int i = 0; i < 4; i++) {
        float invl = 1.0f / l_i[i];
        int t = q0 + 4 * ty + i;
        float* dst = g_attn + (size_t)(b * T_ + t) * D_ + h * HD_ + 4 * tx * 1;
        float4 ov;
        ov.x = o[i][0] * invl;
        ov.y = o[i][1] * invl;
        ov.z = o[i][2] * invl;
        ov.w = o[i][3] * invl;
        *reinterpret_cast<float4*>(dst) = ov;
    }
}

// ---------------------------------------------------------------------------
// Launch
// ---------------------------------------------------------------------------
extern "C" void kernel_launch(void* const* d_in, const int* in_sizes, int n_in,
                              void* d_out, int out_size) {
    const float* x     = (const float*)d_in[0];
    const float* W_qkv = (const float*)d_in[1];
    const float* b_qkv = (const float*)d_in[2];
    const float* W_out = (const float*)d_in[3];
    const float* b_out = (const float*)d_in[4];
    const unsigned char* pmask = (const unsigned char*)d_in[5];
    float* out = (float*)d_out;

    float* qkv_p  = nullptr;
    float* attn_p = nullptr;
    cudaGetSymbolAddress((void**)&qkv_p,  g_qkv);
    cudaGetSymbolAddress((void**)&attn_p, g_attn);

    // 1) QKV = x @ W_qkv + b_qkv        (4096 x 3072 x 1024)
    sgemm_bias_kernel<<<dim3(D3_ / 128, BT_ / 128), 256>>>(
        x, W_qkv, b_qkv, qkv_p, BT_, D3_, D_);

    // 2) transpose + RoPE -> g_q, g_k, g_v
    rope_transform_kernel<<<(B_ * H_ * T_ * 32) / 256, 256>>>();

    // 3) flash attention -> g_attn (B,T,D)
    size_t smem = (size_t)(3 * 64 * 64 + 64 * 65) * sizeof(float);  // ~65.8 KB
    cudaFuncSetAttribute(flash_attn_kernel,
                         cudaFuncAttributeMaxDynamicSharedMemorySize, (int)smem);
    flash_attn_kernel<<<dim3(T_ / 64, B_ * H_), 256, smem>>>(pmask);

    // 4) out = attn @ W_out + b_out     (4096 x 1024 x 1024)
    sgemm_bias_kernel<<<dim3(D_ / 128, BT_ / 128), 256>>>(
        attn_p, W_out, b_out, out, BT_, D_, D_);
}

// round 4
// speedup vs baseline: 1.6607x; 1.6604x over previous
#include <cuda_runtime.h>
#include <cuda_bf16.h>
#include <math.h>
#include <stdint.h>

constexpr int B_  = 2;
constexpr int T_  = 2048;
constexpr int D_  = 1024;
constexpr int H_  = 16;
constexpr int HD_ = 64;
constexpr int BT_ = B_ * T_;
constexpr int D3_ = 3 * D_;
constexpr int NT_ = T_ / 128;   // 16 kv tiles

// Scratch
__device__ float g_qkv[BT_ * D3_];
__device__ float g_attn[BT_ * D_];
__device__ __nv_bfloat16 g_qhi[B_ * H_ * T_ * HD_];
__device__ __nv_bfloat16 g_qlo[B_ * H_ * T_ * HD_];
__device__ __nv_bfloat16 g_khi[B_ * H_ * T_ * HD_];
__device__ __nv_bfloat16 g_klo[B_ * H_ * T_ * HD_];
__device__ __nv_bfloat16 g_vhi[B_ * H_ * T_ * HD_];
__device__ __nv_bfloat16 g_vlo[B_ * H_ * T_ * HD_];

// ============================ PTX helpers ==================================
__device__ __forceinline__ uint32_t smem_u32(const void* p) {
    uint32_t a;
    asm("{ .reg .u64 t; cvta.to.shared.u64 t, %1; cvt.u32.u64 %0, t; }"
        : "=r"(a) : "l"(p));
    return a;
}
#define SWZ(o) ((uint32_t)(o) ^ ((((uint32_t)(o)) >> 3) & 0x70u))

__device__ __forceinline__ void cp16(uint32_t dst, const void* src) {
    asm volatile("cp.async.cg.shared.global [%0], [%1], 16;" :: "r"(dst), "l"(src) : "memory");
}
#define CP_COMMIT() asm volatile("cp.async.commit_group;" ::: "memory")
#define CP_WAIT0()  asm volatile("cp.async.wait_group 0;" ::: "memory")
#define CP_WAIT1()  asm volatile("cp.async.wait_group 1;" ::: "memory")

#define LDSM4(R, a) \
    asm volatile("ldmatrix.sync.aligned.m8n8.x4.shared.b16 {%0,%1,%2,%3}, [%4];" \
        : "=r"((R)[0]), "=r"((R)[1]), "=r"((R)[2]), "=r"((R)[3]) : "r"(a))
#define LDSM4T(R, a) \
    asm volatile("ldmatrix.sync.aligned.m8n8.x4.trans.shared.b16 {%0,%1,%2,%3}, [%4];" \
        : "=r"((R)[0]), "=r"((R)[1]), "=r"((R)[2]), "=r"((R)[3]) : "r"(a))

__device__ __forceinline__ void mma16816(float* c, const uint32_t* a,
                                         uint32_t b0, uint32_t b1) {
    asm volatile("mma.sync.aligned.m16n8k16.row.col.f32.bf16.bf16.f32 "
        "{%0,%1,%2,%3}, {%4,%5,%6,%7}, {%8,%9}, {%0,%1,%2,%3};"
        : "+f"(c[0]), "+f"(c[1]), "+f"(c[2]), "+f"(c[3])
        : "r"(a[0]), "r"(a[1]), "r"(a[2]), "r"(a[3]), "r"(b0), "r"(b1));
}

__device__ __forceinline__ uint32_t packbf2(float x, float y) {
    __nv_bfloat16 hx = __float2bfloat16(x);
    __nv_bfloat16 hy = __float2bfloat16(y);
    return (uint32_t)__bfloat16_as_ushort(hx)
         | ((uint32_t)__bfloat16_as_ushort(hy) << 16);
}

// ======================= fp32 SGEMM (unchanged) ============================
__global__ void sgemm_bias_kernel(const float* __restrict__ A,
                                  const float* __restrict__ Bm,
                                  const float* __restrict__ bias,
                                  float* __restrict__ C,
                                  int M, int N, int K) {
    constexpr int BK = 8, TM = 8, TN = 8;
    __shared__ float As[BK][128];
    __shared__ float Bs[BK][128];
    const int tid = threadIdx.x;
    const int tr = tid >> 4, tc = tid & 15;
    const int rowBase = blockIdx.y * 128, colBase = blockIdx.x * 128;
    const int aRow = tid >> 1, aCol = (tid & 1) << 2;
    const int bRow = tid >> 5, bCol = (tid & 31) << 2;
    const float* Aptr = A + (size_t)(rowBase + aRow) * K + aCol;
    const float* Bptr = Bm + (size_t)bRow * N + colBase + bCol;

    float acc[TM][TN];
#pragma unroll
    for (int i = 0; i < TM; i++)
#pragma unroll
        for (int j = 0; j < TN; j++) acc[i][j] = 0.0f;

    for (int k0 = 0; k0 < K; k0 += BK) {
        float4 a4 = *reinterpret_cast<const float4*>(Aptr + k0);
        float4 b4 = *reinterpret_cast<const float4*>(Bptr + (size_t)k0 * N);
        As[aCol + 0][aRow] = a4.x; As[aCol + 1][aRow] = a4.y;
        As[aCol + 2][aRow] = a4.z; As[aCol + 3][aRow] = a4.w;
        *reinterpret_cast<float4*>(&Bs[bRow][bCol]) = b4;
        __syncthreads();
#pragma unroll
        for (int k = 0; k < BK; k++) {
            float ra[TM], rb[TN];
#pragma unroll
            for (int i = 0; i < TM; i++) ra[i] = As[k][tr * TM + i];
#pragma unroll
            for (int j = 0; j < TN; j++) rb[j] = Bs[k][tc * TN + j];
#pragma unroll
            for (int i = 0; i < TM; i++)
#pragma unroll
                for (int j = 0; j < TN; j++)
                    acc[i][j] = fmaf(ra[i], rb[j], acc[i][j]);
        }
        __syncthreads();
    }
#pragma unroll
    for (int i = 0; i < TM; i++) {
        int r = rowBase + tr * TM + i;
#pragma unroll
        for (int j = 0; j < TN; j += 4) {
            int c = colBase + tc * TN + j;
            float4 ov;
            ov.x = acc[i][j+0] + bias[c+0]; ov.y = acc[i][j+1] + bias[c+1];
            ov.z = acc[i][j+2] + bias[c+2]; ov.w = acc[i][j+3] + bias[c+3];
            *reinterpret_cast<float4*>(&C[(size_t)r * N + c]) = ov;
        }
    }
}

// ============ RoPE + transpose -> bf16 hi/lo splits for q,k,v ==============
__device__ __forceinline__ void split_store(__nv_bfloat16* hi, __nv_bfloat16* lo,
                                            size_t i, float v) {
    __nv_bfloat16 h = __float2bfloat16(v);
    hi[i] = h;
    lo[i] = __float2bfloat16(v - __bfloat162float(h));
}

__global__ void rope_bf16_kernel() {
    int idx = blockIdx.x * blockDim.x + threadIdx.x;
    int d = idx & 31;
    int t = (idx >> 5) & (T_ - 1);
    int h = (idx >> 16) & (H_ - 1);
    int b = idx >> 20;
    const float* src = g_qkv + (size_t)(b * T_ + t) * D3_ + h * HD_;
    float expo = (float)(2 * d) * (1.0f / (float)HD_);
    float inv  = 1.0f / powf(10000.0f, expo);
    float s, c;
    sincosf((float)t * inv, &s, &c);
    size_t dst = ((size_t)(b * H_ + h) * T_ + t) * HD_;
    float q1 = src[d], q2 = src[d + 32];
    split_store(g_qhi, g_qlo, dst + d,      q1 * c - q2 * s);
    split_store(g_qhi, g_qlo, dst + d + 32, q2 * c + q1 * s);
    float k1 = src[D_ + d], k2 = src[D_ + d + 32];
    split_store(g_khi, g_klo, dst + d,      k1 * c - k2 * s);
    split_store(g_khi, g_klo, dst + d + 32, k2 * c + k1 * s);
    split_store(g_vhi, g_vlo, dst + d,      src[2 * D_ + d]);
    split_store(g_vhi, g_vlo, dst + d + 32, src[2 * D_ + d + 32]);
}

// ================= mma.sync flash attention (bf16 split) ===================
// SMEM map (from 1024-aligned base); all tiles: 128 rows x 128B, SW128 swizzle
constexpr uint32_t SM_QHI = 0;
constexpr uint32_t SM_QLO = 16384;
constexpr uint32_t SM_KV  = 32768;                 // + buf*65536
constexpr uint32_t KV_KHI = 0, KV_KLO = 16384, KV_VHI = 32768, KV_VLO = 49152;
constexpr uint32_t SM_MASK = 163840;               // T_ bytes
constexpr uint32_t SMEM_BYTES = 165888 + 1024;

__device__ __forceinline__ void load_kv_tile(
    uint32_t smem, int buf, int k0, int tid,
    const __nv_bfloat16* gkh, const __nv_bfloat16* gkl,
    const __nv_bfloat16* gvh, const __nv_bfloat16* gvl) {
    uint32_t base = smem + SM_KV + (uint32_t)buf * 65536u;
#pragma unroll
    for (int c = tid; c < 1024; c += 256) {
        int row = c >> 3, off = c & 7;
        uint32_t sw = SWZ(row * 128 + off * 16);
        size_t g = (size_t)(k0 + row) * HD_ + off * 8;
        cp16(base + KV_KHI + sw, gkh + g);
        cp16(base + KV_KLO + sw, gkl + g);
        cp16(base + KV_VHI + sw, gvh + g);
        cp16(base + KV_VLO + sw, gvl + g);
    }
}

__global__ __launch_bounds__(256, 1)
void attn_mma_kernel(const unsigned char* __restrict__ mask) {
    extern __shared__ unsigned char smraw[];
    uint32_t smem = (smem_u32(smraw) + 1023u) & ~1023u;
    unsigned char* smbyte = smraw + (smem - smem_u32(smraw));

    const int tid  = threadIdx.x;
    const int warp = tid >> 5, lane = tid & 31;
    const int grp  = lane >> 3, rIn = lane & 7;
    const int bh = blockIdx.y, b = bh >> 4, h = bh & 15;
    const int q0 = blockIdx.x * 128;
    const int wrow = warp * 16;

    const size_t hb = (size_t)bh * T_ * HD_;
    const __nv_bfloat16* gqh = g_qhi + hb + (size_t)q0 * HD_;
    const __nv_bfloat16* gql = g_qlo + hb + (size_t)q0 * HD_;
    const __nv_bfloat16* gkh = g_khi + hb;
    const __nv_bfloat16* gkl = g_klo + hb;
    const __nv_bfloat16* gvh = g_vhi + hb;
    const __nv_bfloat16* gvl = g_vlo + hb;

    // group 0: Q tiles + mask + KV tile 0
#pragma unroll
    for (int c = tid; c < 1024; c += 256) {
        int row = c >> 3, off = c & 7;
        uint32_t sw = SWZ(row * 128 + off * 16);
        size_t g = (size_t)row * HD_ + off * 8;
        cp16(smem + SM_QHI + sw, gqh + g);
        cp16(smem + SM_QLO + sw, gql + g);
    }
    if (tid < 128) cp16(smem + SM_MASK + tid * 16, mask + b * T_ + tid * 16);
    load_kv_tile(smem, 0, 0, tid, gkh, gkl, gvh, gvl);
    CP_COMMIT();
    CP_WAIT0();
    __syncthreads();

    // Q fragments, resident across all KV tiles (A-operand, m16n8k16)
    uint32_t qh[4][4], ql[4][4];
    const uint32_t qoff = (uint32_t)((wrow + rIn + (grp & 1) * 8) * 128 + (grp >> 1) * 16);
#pragma unroll
    for (int kk = 0; kk < 4; kk++) {
        LDSM4(qh[kk], smem + SM_QHI + SWZ(qoff + kk * 32));
        LDSM4(ql[kk], smem + SM_QLO + SWZ(qoff + kk * 32));
    }

    float o[8][4];
#pragma unroll
    for (int j = 0; j < 8; j++)
#pragma unroll
        for (int i = 0; i < 4; i++) o[j][i] = 0.0f;
    float ls0 = 0.0f, ls1 = 0.0f;

    const uint32_t kb = (uint32_t)(rIn * 128 + grp * 16);    // K-frag thread offset
    const uint32_t vb = (uint32_t)(grp * 1024 + rIn * 128);  // V-frag thread offset
    const int mcol0 = 2 * (lane & 3);

    for (int t = 0; t < NT_; t++) {
        const uint32_t kvb = smem + SM_KV + (uint32_t)(t & 1) * 65536u;

        __syncthreads();   // everyone done reading buf^1 (tile t-1)
        if (t + 1 < NT_) {
            load_kv_tile(smem, (t + 1) & 1, (t + 1) * 128, tid, gkh, gkl, gvh, gvl);
            CP_COMMIT();
            CP_WAIT1();    // tile t landed (tile t+1 may be in flight)
        } else {
            CP_WAIT0();
        }
        __syncthreads();   // tile t visible to all threads

        // ---- S = Q K^T (16 q rows x 128 kv per warp) ----
        float c[16][4];
#pragma unroll
        for (int j = 0; j < 16; j++)
#pragma unroll
            for (int i = 0; i < 4; i++) c[j][i] = 0.0f;

#pragma unroll
        for (int kp = 0; kp < 2; kp++) {
#pragma unroll
            for (int j = 0; j < 16; j++) {
                uint32_t kh[4], kl[4];
                uint32_t off = (uint32_t)(1024 * j + kp * 64) + kb;
                LDSM4(kh, kvb + KV_KHI + SWZ(off));
                LDSM4(kl, kvb + KV_KLO + SWZ(off));
                mma16816(c[j], qh[2 * kp],     kh[0], kh[1]);
                mma16816(c[j], qh[2 * kp],     kl[0], kl[1]);
                mma16816(c[j], ql[2 * kp],     kh[0], kh[1]);
                mma16816(c[j], qh[2 * kp + 1], kh[2], kh[3]);
                mma16816(c[j], qh[2 * kp + 1], kl[2], kl[3]);
                mma16816(c[j], ql[2 * kp + 1], kh[2], kh[3]);
            }
        }

        // ---- softmax (p = exp(s/8), no max) + PV, fused per k-quad ----
        const unsigned char* mk = smbyte + SM_MASK + t * 128;
#pragma unroll
        for (int p = 0; p < 4; p++) {
            uint32_t ph[2][4], pl[2][4];
#pragma unroll
            for (int q2 = 0; q2 < 2; q2++) {
#pragma unroll
                for (int jj = 0; jj < 2; jj++) {
                    int j = 4 * p + 2 * q2 + jj;
                    int cg = 8 * j + mcol0;
                    bool m0 = mk[cg], m1 = mk[cg + 1];
                    float p0 = m0 ? 0.0f : __expf(c[j][0] * 0.125f);
                    float p1 = m1 ? 0.0f : __expf(c[j][1] * 0.125f);
                    float p2 = m0 ? 0.0f : __expf(c[j][2] * 0.125f);
                    float p3 = m1 ? 0.0f : __expf(c[j][3] * 0.125f);
                    ls0 += p0 + p1;
                    ls1 += p2 + p3;
                    __nv_bfloat16 h0 = __float2bfloat16(p0);
                    __nv_bfloat16 h1 = __float2bfloat16(p1);
                    __nv_bfloat16 h2 = __float2bfloat16(p2);
                    __nv_bfloat16 h3 = __float2bfloat16(p3);
                    ph[q2][2 * jj + 0] = (uint32_t)__bfloat16_as_ushort(h0)
                                       | ((uint32_t)__bfloat16_as_ushort(h1) << 16);
                    ph[q2][2 * jj + 1] = (uint32_t)__bfloat16_as_ushort(h2)
                                       | ((uint32_t)__bfloat16_as_ushort(h3) << 16);
                    pl[q2][2 * jj + 0] = packbf2(p0 - __bfloat162float(h0),
                                                 p1 - __bfloat162float(h1));
                    pl[q2][2 * jj + 1] = packbf2(p2 - __bfloat162float(h2),
                                                 p3 - __bfloat162float(h3));
                }
            }
#pragma unroll
            for (int jh = 0; jh < 8; jh++) {
                uint32_t vh[4], vl[4];
                uint32_t off = (uint32_t)(4096 * p + 16 * jh) + vb;
                LDSM4T(vh, kvb + KV_VHI + SWZ(off));
                LDSM4T(vl, kvb + KV_VLO + SWZ(off));
                mma16816(o[jh], ph[0], vh[0], vh[1]);
                mma16816(o[jh], ph[0], vl[0], vl[1]);
                mma16816(o[jh], pl[0], vh[0], vh[1]);
                mma16816(o[jh], ph[1], vh[2], vh[3]);
                mma16816(o[jh], ph[1], vl[2], vl[3]);
                mma16816(o[jh], pl[1], vh[2], vh[3]);
            }
        }
    }

    // row sums across the quad (lanes sharing lane>>2)
    ls0 += __shfl_xor_sync(0xffffffffu, ls0, 1);
    ls0 += __shfl_xor_sync(0xffffffffu, ls0, 2);
    ls1 += __shfl_xor_sync(0xffffffffu, ls1, 1);
    ls1 += __shfl_xor_sync(0xffffffffu, ls1, 2);
    float i0 = 1.0f / ls0, i1 = 1.0f / ls1;

    int r = q0 + wrow + (lane >> 2);
    float* dst = g_attn + (size_t)(b * T_ + r) * D_ + h * HD_ + mcol0;
#pragma unroll
    for (int jh = 0; jh < 8; jh++) {
        float2 v0 = make_float2(o[jh][0] * i0, o[jh][1] * i0);
        float2 v1 = make_float2(o[jh][2] * i1, o[jh][3] * i1);
        *reinterpret_cast<float2*>(dst + 8 * jh)           = v0;
        *reinterpret_cast<float2*>(dst + 8 * jh + 8 * D_)  = v1;
    }
}

// ============================== Launch =====================================
extern "C" void kernel_launch(void* const* d_in, const int* in_sizes, int n_in,
                              void* d_out, int out_size) {
    const float* x     = (const float*)d_in[0];
    const float* W_qkv = (const float*)d_in[1];
    const float* b_qkv = (const float*)d_in[2];
    const float* W_out = (const float*)d_in[3];
    const float* b_out = (const float*)d_in[4];
    const unsigned char* pmask = (const unsigned char*)d_in[5];
    float* out = (float*)d_out;

    float* qkv_p = nullptr;
    float* attn_p = nullptr;
    cudaGetSymbolAddress((void**)&qkv_p, g_qkv);
    cudaGetSymbolAddress((void**)&attn_p, g_attn);

    // 1) QKV = x @ W_qkv + b_qkv
    sgemm_bias_kernel<<<dim3(D3_ / 128, BT_ / 128), 256>>>(
        x, W_qkv, b_qkv, qkv_p, BT_, D3_, D_);

    // 2) RoPE + bf16 hi/lo splits (q, k, v)
    rope_bf16_kernel<<<(B_ * H_ * T_ * 32) / 256, 256>>>();

    // 3) mma.sync flash attention -> g_attn (B,T,D)
    cudaFuncSetAttribute(attn_mma_kernel,
                         cudaFuncAttributeMaxDynamicSharedMemorySize,
                         (int)SMEM_BYTES);
    attn_mma_kernel<<<dim3(T_ / 128, B_ * H_), 256, SMEM_BYTES>>>(pmask);

    // 4) out = attn @ W_out + b_out
    sgemm_bias_kernel<<<dim3(D_ / 128, BT_ / 128), 256>>>(
        attn_p, W_out, b_out, out, BT_, D_, D_);
}

// round 5
// speedup vs baseline: 3.2138x; 1.9352x over previous
#include <cuda_runtime.h>
#include <cuda_bf16.h>
#include <math.h>
#include <stdint.h>

constexpr int B_  = 2;
constexpr int T_  = 2048;
constexpr int D_  = 1024;
constexpr int H_  = 16;
constexpr int HD_ = 64;
constexpr int BT_ = B_ * T_;
constexpr int D3_ = 3 * D_;
constexpr int NT_ = T_ / 128;   // 16 kv tiles

// Scratch
__device__ float g_qkv[BT_ * D3_];
__device__ float g_attn[BT_ * D_];
__device__ __nv_bfloat16 g_qhi[B_ * H_ * T_ * HD_];
__device__ __nv_bfloat16 g_qlo[B_ * H_ * T_ * HD_];
__device__ __nv_bfloat16 g_khi[B_ * H_ * T_ * HD_];
__device__ __nv_bfloat16 g_klo[B_ * H_ * T_ * HD_];
__device__ __nv_bfloat16 g_vhi[B_ * H_ * T_ * HD_];
__device__ __nv_bfloat16 g_vlo[B_ * H_ * T_ * HD_];
// GEMM operand splits (A reused for x and attn; B reused for W_qkv and W_out)
__device__ __nv_bfloat16 g_gahi[BT_ * D_];
__device__ __nv_bfloat16 g_galo[BT_ * D_];
__device__ __nv_bfloat16 g_gbhi[D_ * D3_];
__device__ __nv_bfloat16 g_gblo[D_ * D3_];

// ============================ PTX helpers ==================================
__device__ __forceinline__ uint32_t smem_u32(const void* p) {
    uint32_t a;
    asm("{ .reg .u64 t; cvta.to.shared.u64 t, %1; cvt.u32.u64 %0, t; }"
        : "=r"(a) : "l"(p));
    return a;
}
#define SWZ(o) ((uint32_t)(o) ^ ((((uint32_t)(o)) >> 3) & 0x70u))

__device__ __forceinline__ void cp16(uint32_t dst, const void* src) {
    asm volatile("cp.async.cg.shared.global [%0], [%1], 16;" :: "r"(dst), "l"(src) : "memory");
}
#define CP_COMMIT() asm volatile("cp.async.commit_group;" ::: "memory")
#define CP_WAIT0()  asm volatile("cp.async.wait_group 0;" ::: "memory")
#define CP_WAIT1()  asm volatile("cp.async.wait_group 1;" ::: "memory")

#define LDSM4(R, a) \
    asm volatile("ldmatrix.sync.aligned.m8n8.x4.shared.b16 {%0,%1,%2,%3}, [%4];" \
        : "=r"((R)[0]), "=r"((R)[1]), "=r"((R)[2]), "=r"((R)[3]) : "r"(a))
#define LDSM4T(R, a) \
    asm volatile("ldmatrix.sync.aligned.m8n8.x4.trans.shared.b16 {%0,%1,%2,%3}, [%4];" \
        : "=r"((R)[0]), "=r"((R)[1]), "=r"((R)[2]), "=r"((R)[3]) : "r"(a))

__device__ __forceinline__ void mma16816(float* c, const uint32_t* a,
                                         uint32_t b0, uint32_t b1) {
    asm volatile("mma.sync.aligned.m16n8k16.row.col.f32.bf16.bf16.f32 "
        "{%0,%1,%2,%3}, {%4,%5,%6,%7}, {%8,%9}, {%0,%1,%2,%3};"
        : "+f"(c[0]), "+f"(c[1]), "+f"(c[2]), "+f"(c[3])
        : "r"(a[0]), "r"(a[1]), "r"(a[2]), "r"(a[3]), "r"(b0), "r"(b1));
}

__device__ __forceinline__ uint32_t packbf2(float x, float y) {
    __nv_bfloat16 hx = __float2bfloat16(x);
    __nv_bfloat16 hy = __float2bfloat16(y);
    return (uint32_t)__bfloat16_as_ushort(hx)
         | ((uint32_t)__bfloat16_as_ushort(hy) << 16);
}

// ===================== elementwise hi/lo split =============================
__global__ void split_kernel(const float4* __restrict__ src,
                             uint32_t* __restrict__ hi,
                             uint32_t* __restrict__ lo, int n4) {
    int i = blockIdx.x * blockDim.x + threadIdx.x;
    if (i >= n4) return;
    float4 v = src[i];
    __nv_bfloat16 h0 = __float2bfloat16(v.x);
    __nv_bfloat16 h1 = __float2bfloat16(v.y);
    __nv_bfloat16 h2 = __float2bfloat16(v.z);
    __nv_bfloat16 h3 = __float2bfloat16(v.w);
    hi[2 * i]     = (uint32_t)__bfloat16_as_ushort(h0)
                  | ((uint32_t)__bfloat16_as_ushort(h1) << 16);
    hi[2 * i + 1] = (uint32_t)__bfloat16_as_ushort(h2)
                  | ((uint32_t)__bfloat16_as_ushort(h3) << 16);
    lo[2 * i]     = packbf2(v.x - __bfloat162float(h0), v.y - __bfloat162float(h1));
    lo[2 * i + 1] = packbf2(v.z - __bfloat162float(h2), v.w - __bfloat162float(h3));
}

// ================= split-bf16 tensor-core GEMM =============================
// C[M,N] = (Ahi+Alo)[M,K] @ (Bhi+Blo)[K,N] + bias, 3-product split.
// BM=128, BN=128, BK=64. 256 threads = 8 warps (2 row x 4 col), warp m64n32.
constexpr uint32_t GA_HI = 0;          // 128 x 64 bf16, 128B rows, SW128
constexpr uint32_t GA_LO = 16384;
constexpr uint32_t GB_HI = 32768;      // 2 halves x (64 x 64 bf16) 128B rows
constexpr uint32_t GB_LO = 49152;
constexpr uint32_t GBUF  = 65536;      // buffer stride
constexpr uint32_t GEMM_SMEM = 131072;

__device__ __forceinline__ void gemm_load(
    uint32_t base, int tid, int rowBase, int colBase, int k0, int K, int N,
    const __nv_bfloat16* Ahi, const __nv_bfloat16* Alo,
    const __nv_bfloat16* Bhi, const __nv_bfloat16* Blo) {
#pragma unroll
    for (int c = tid; c < 1024; c += 256) {          // A: 128 rows x 8 chunks
        int row = c >> 3, off = c & 7;
        uint32_t sw = SWZ(row * 128 + off * 16);
        size_t g = (size_t)(rowBase + row) * K + k0 + off * 8;
        cp16(base + GA_HI + sw, Ahi + g);
        cp16(base + GA_LO + sw, Alo + g);
    }
#pragma unroll
    for (int c = tid; c < 1024; c += 256) {          // B: 2 halves x 64 rows x 8
        int half = c >> 9, cc = c & 511;
        int row = cc >> 3, off = cc & 7;
        uint32_t sw = (uint32_t)(half * 8192) + SWZ(row * 128 + off * 16);
        size_t g = (size_t)(k0 + row) * N + colBase + half * 64 + off * 8;
        cp16(base + GB_HI + sw, Bhi + g);
        cp16(base + GB_LO + sw, Blo + g);
    }
}

__global__ __launch_bounds__(256, 1)
void gemm_bf16_kernel(const __nv_bfloat16* __restrict__ Ahi,
                      const __nv_bfloat16* __restrict__ Alo,
                      const __nv_bfloat16* __restrict__ Bhi,
                      const __nv_bfloat16* __restrict__ Blo,
                      const float* __restrict__ bias,
                      float* __restrict__ C, int M, int N, int K) {
    extern __shared__ unsigned char smraw[];
    uint32_t smem = (smem_u32(smraw) + 1023u) & ~1023u;

    const int tid = threadIdx.x;
    const int warp = tid >> 5, lane = tid & 31;
    const int grp = lane >> 3, rIn = lane & 7;
    const int rowBase = blockIdx.y * 128, colBase = blockIdx.x * 128;
    const int wrow = (warp >> 2) * 64, wc = (warp & 3) * 32;
    const int halfsel = wc >> 6;
    const int cb = (wc & 63) >> 3;
    const int NIT = K / 64;

    const uint32_t aoff = (uint32_t)((wrow + rIn + (grp & 1) * 8) * 128 + (grp >> 1) * 16);
    const uint32_t boff = (uint32_t)(grp * 1024 + rIn * 128);

    float acc[4][4][4];
#pragma unroll
    for (int m = 0; m < 4; m++)
#pragma unroll
        for (int n = 0; n < 4; n++)
#pragma unroll
            for (int i = 0; i < 4; i++) acc[m][n][i] = 0.0f;

    gemm_load(smem, tid, rowBase, colBase, 0, K, N, Ahi, Alo, Bhi, Blo);
    CP_COMMIT();

    for (int it = 0; it < NIT; it++) {
        __syncthreads();
        if (it + 1 < NIT) {
            gemm_load(smem + ((it + 1) & 1) * GBUF, tid, rowBase, colBase,
                      (it + 1) * 64, K, N, Ahi, Alo, Bhi, Blo);
            CP_COMMIT();
            CP_WAIT1();
        } else {
            CP_WAIT0();
        }
        __syncthreads();

        const uint32_t base = smem + (uint32_t)(it & 1) * GBUF;
        const uint32_t Ah = base + GA_HI, Al = base + GA_LO;
        const uint32_t Bh = base + GB_HI + halfsel * 8192;
        const uint32_t Bl = base + GB_LO + halfsel * 8192;

#pragma unroll
        for (int kh = 0; kh < 2; kh++) {
            uint32_t bh[4][4], bl[4][4];
#pragma unroll
            for (int n = 0; n < 4; n++) {
                uint32_t o = boff + (uint32_t)(kh * 4096 + (cb + n) * 16);
                LDSM4T(bh[n], Bh + SWZ(o));
                LDSM4T(bl[n], Bl + SWZ(o));
            }
#pragma unroll
            for (int s = 0; s < 2; s++) {
                uint32_t ah[4][4], al[4][4];
#pragma unroll
                for (int m = 0; m < 4; m++) {
                    uint32_t o = aoff + (uint32_t)(m * 2048 + (kh * 2 + s) * 32);
                    LDSM4(ah[m], Ah + SWZ(o));
                    LDSM4(al[m], Al + SWZ(o));
                }
#pragma unroll
                for (int m = 0; m < 4; m++)
#pragma unroll
                    for (int n = 0; n < 4; n++) {
                        mma16816(acc[m][n], ah[m], bh[n][2 * s], bh[n][2 * s + 1]);
                        mma16816(acc[m][n], ah[m], bl[n][2 * s], bl[n][2 * s + 1]);
                        mma16816(acc[m][n], al[m], bh[n][2 * s], bh[n][2 * s + 1]);
                    }
            }
        }
    }

    // epilogue: C = acc + bias
#pragma unroll
    for (int m = 0; m < 4; m++) {
        int r0 = rowBase + wrow + m * 16 + (lane >> 2);
#pragma unroll
        for (int n = 0; n < 4; n++) {
            int col = colBase + wc + n * 8 + 2 * (lane & 3);
            float bx = bias[col], by = bias[col + 1];
            float2 v0 = make_float2(acc[m][n][0] + bx, acc[m][n][1] + by);
            float2 v1 = make_float2(acc[m][n][2] + bx, acc[m][n][3] + by);
            *reinterpret_cast<float2*>(&C[(size_t)r0 * N + col])       = v0;
            *reinterpret_cast<float2*>(&C[(size_t)(r0 + 8) * N + col]) = v1;
        }
    }
}

// ============ RoPE + transpose -> bf16 hi/lo splits for q,k,v ==============
__device__ __forceinline__ void split_store(__nv_bfloat16* hi, __nv_bfloat16* lo,
                                            size_t i, float v) {
    __nv_bfloat16 h = __float2bfloat16(v);
    hi[i] = h;
    lo[i] = __float2bfloat16(v - __bfloat162float(h));
}

__global__ void rope_bf16_kernel() {
    int idx = blockIdx.x * blockDim.x + threadIdx.x;
    int d = idx & 31;
    int t = (idx >> 5) & (T_ - 1);
    int h = (idx >> 16) & (H_ - 1);
    int b = idx >> 20;
    const float* src = g_qkv + (size_t)(b * T_ + t) * D3_ + h * HD_;
    float expo = (float)(2 * d) * (1.0f / (float)HD_);
    float inv  = 1.0f / powf(10000.0f, expo);
    float s, c;
    sincosf((float)t * inv, &s, &c);
    size_t dst = ((size_t)(b * H_ + h) * T_ + t) * HD_;
    float q1 = src[d], q2 = src[d + 32];
    split_store(g_qhi, g_qlo, dst + d,      q1 * c - q2 * s);
    split_store(g_qhi, g_qlo, dst + d + 32, q2 * c + q1 * s);
    float k1 = src[D_ + d], k2 = src[D_ + d + 32];
    split_store(g_khi, g_klo, dst + d,      k1 * c - k2 * s);
    split_store(g_khi, g_klo, dst + d + 32, k2 * c + k1 * s);
    split_store(g_vhi, g_vlo, dst + d,      src[2 * D_ + d]);
    split_store(g_vhi, g_vlo, dst + d + 32, src[2 * D_ + d + 32]);
}

// ================= mma.sync flash attention (unchanged R4) =================
constexpr uint32_t SM_QHI = 0;
constexpr uint32_t SM_QLO = 16384;
constexpr uint32_t SM_KV  = 32768;                 // + buf*65536
constexpr uint32_t KV_KHI = 0, KV_KLO = 16384, KV_VHI = 32768, KV_VLO = 49152;
constexpr uint32_t SM_MASK = 163840;               // T_ bytes
constexpr uint32_t SMEM_BYTES = 165888 + 1024;

__device__ __forceinline__ void load_kv_tile(
    uint32_t smem, int buf, int k0, int tid,
    const __nv_bfloat16* gkh, const __nv_bfloat16* gkl,
    const __nv_bfloat16* gvh, const __nv_bfloat16* gvl) {
    uint32_t base = smem + SM_KV + (uint32_t)buf * 65536u;
#pragma unroll
    for (int c = tid; c < 1024; c += 256) {
        int row = c >> 3, off = c & 7;
        uint32_t sw = SWZ(row * 128 + off * 16);
        size_t g = (size_t)(k0 + row) * HD_ + off * 8;
        cp16(base + KV_KHI + sw, gkh + g);
        cp16(base + KV_KLO + sw, gkl + g);
        cp16(base + KV_VHI + sw, gvh + g);
        cp16(base + KV_VLO + sw, gvl + g);
    }
}

__global__ __launch_bounds__(256, 1)
void attn_mma_kernel(const unsigned char* __restrict__ mask) {
    extern __shared__ unsigned char smraw[];
    uint32_t smem = (smem_u32(smraw) + 1023u) & ~1023u;
    unsigned char* smbyte = smraw + (smem - smem_u32(smraw));

    const int tid  = threadIdx.x;
    const int warp = tid >> 5, lane = tid & 31;
    const int grp  = lane >> 3, rIn = lane & 7;
    const int bh = blockIdx.y, b = bh >> 4, h = bh & 15;
    const int q0 = blockIdx.x * 128;
    const int wrow = warp * 16;

    const size_t hb = (size_t)bh * T_ * HD_;
    const __nv_bfloat16* gqh = g_qhi + hb + (size_t)q0 * HD_;
    const __nv_bfloat16* gql = g_qlo + hb + (size_t)q0 * HD_;
    const __nv_bfloat16* gkh = g_khi + hb;
    const __nv_bfloat16* gkl = g_klo + hb;
    const __nv_bfloat16* gvh = g_vhi + hb;
    const __nv_bfloat16* gvl = g_vlo + hb;

#pragma unroll
    for (int c = tid; c < 1024; c += 256) {
        int row = c >> 3, off = c & 7;
        uint32_t sw = SWZ(row * 128 + off * 16);
        size_t g = (size_t)row * HD_ + off * 8;
        cp16(smem + SM_QHI + sw, gqh + g);
        cp16(smem + SM_QLO + sw, gql + g);
    }
    if (tid < 128) cp16(smem + SM_MASK + tid * 16, mask + b * T_ + tid * 16);
    load_kv_tile(smem, 0, 0, tid, gkh, gkl, gvh, gvl);
    CP_COMMIT();
    CP_WAIT0();
    __syncthreads();

    uint32_t qh[4][4], ql[4][4];
    const uint32_t qoff = (uint32_t)((wrow + rIn + (grp & 1) * 8) * 128 + (grp >> 1) * 16);
#pragma unroll
    for (int kk = 0; kk < 4; kk++) {
        LDSM4(qh[kk], smem + SM_QHI + SWZ(qoff + kk * 32));
        LDSM4(ql[kk], smem + SM_QLO + SWZ(qoff + kk * 32));
    }

    float o[8][4];
#pragma unroll
    for (int j = 0; j < 8; j++)
#pragma unroll
        for (int i = 0; i < 4; i++) o[j][i] = 0.0f;
    float ls0 = 0.0f, ls1 = 0.0f;

    const uint32_t kb = (uint32_t)(rIn * 128 + grp * 16);
    const uint32_t vb = (uint32_t)(grp * 1024 + rIn * 128);
    const int mcol0 = 2 * (lane & 3);

    for (int t = 0; t < NT_; t++) {
        const uint32_t kvb = smem + SM_KV + (uint32_t)(t & 1) * 65536u;

        __syncthreads();
        if (t + 1 < NT_) {
            load_kv_tile(smem, (t + 1) & 1, (t + 1) * 128, tid, gkh, gkl, gvh, gvl);
            CP_COMMIT();
            CP_WAIT1();
        } else {
            CP_WAIT0();
        }
        __syncthreads();

        float c[16][4];
#pragma unroll
        for (int j = 0; j < 16; j++)
#pragma unroll
            for (int i = 0; i < 4; i++) c[j][i] = 0.0f;

#pragma unroll
        for (int kp = 0; kp < 2; kp++) {
#pragma unroll
            for (int j = 0; j < 16; j++) {
                uint32_t kh[4], kl[4];
                uint32_t off = (uint32_t)(1024 * j + kp * 64) + kb;
                LDSM4(kh, kvb + KV_KHI + SWZ(off));
                LDSM4(kl, kvb + KV_KLO + SWZ(off));
                mma16816(c[j], qh[2 * kp],     kh[0], kh[1]);
                mma16816(c[j], qh[2 * kp],     kl[0], kl[1]);
                mma16816(c[j], ql[2 * kp],     kh[0], kh[1]);
                mma16816(c[j], qh[2 * kp + 1], kh[2], kh[3]);
                mma16816(c[j], qh[2 * kp + 1], kl[2], kl[3]);
                mma16816(c[j], ql[2 * kp + 1], kh[2], kh[3]);
            }
        }

        const unsigned char* mk = smbyte + SM_MASK + t * 128;
#pragma unroll
        for (int p = 0; p < 4; p++) {
            uint32_t ph[2][4], pl[2][4];
#pragma unroll
            for (int q2 = 0; q2 < 2; q2++) {
#pragma unroll
                for (int jj = 0; jj < 2; jj++) {
                    int j = 4 * p + 2 * q2 + jj;
                    int cg = 8 * j + mcol0;
                    bool m0 = mk[cg], m1 = mk[cg + 1];
                    float p0 = m0 ? 0.0f : __expf(c[j][0] * 0.125f);
                    float p1 = m1 ? 0.0f : __expf(c[j][1] * 0.125f);
                    float p2 = m0 ? 0.0f : __expf(c[j][2] * 0.125f);
                    float p3 = m1 ? 0.0f : __expf(c[j][3] * 0.125f);
                    ls0 += p0 + p1;
                    ls1 += p2 + p3;
                    __nv_bfloat16 h0 = __float2bfloat16(p0);
                    __nv_bfloat16 h1 = __float2bfloat16(p1);
                    __nv_bfloat16 h2 = __float2bfloat16(p2);
                    __nv_bfloat16 h3 = __float2bfloat16(p3);
                    ph[q2][2 * jj + 0] = (uint32_t)__bfloat16_as_ushort(h0)
                                       | ((uint32_t)__bfloat16_as_ushort(h1) << 16);
                    ph[q2][2 * jj + 1] = (uint32_t)__bfloat16_as_ushort(h2)
                                       | ((uint32_t)__bfloat16_as_ushort(h3) << 16);
                    pl[q2][2 * jj + 0] = packbf2(p0 - __bfloat162float(h0),
                                                 p1 - __bfloat162float(h1));
                    pl[q2][2 * jj + 1] = packbf2(p2 - __bfloat162float(h2),
                                                 p3 - __bfloat162float(h3));
                }
            }
#pragma unroll
            for (int jh = 0; jh < 8; jh++) {
                uint32_t vh[4], vl[4];
                uint32_t off = (uint32_t)(4096 * p + 16 * jh) + vb;
                LDSM4T(vh, kvb + KV_VHI + SWZ(off));
                LDSM4T(vl, kvb + KV_VLO + SWZ(off));
                mma16816(o[jh], ph[0], vh[0], vh[1]);
                mma16816(o[jh], ph[0], vl[0], vl[1]);
                mma16816(o[jh], pl[0], vh[0], vh[1]);
                mma16816(o[jh], ph[1], vh[2], vh[3]);
                mma16816(o[jh], ph[1], vl[2], vl[3]);
                mma16816(o[jh], pl[1], vh[2], vh[3]);
            }
        }
    }

    ls0 += __shfl_xor_sync(0xffffffffu, ls0, 1);
    ls0 += __shfl_xor_sync(0xffffffffu, ls0, 2);
    ls1 += __shfl_xor_sync(0xffffffffu, ls1, 1);
    ls1 += __shfl_xor_sync(0xffffffffu, ls1, 2);
    float i0 = 1.0f / ls0, i1 = 1.0f / ls1;

    int r = q0 + wrow + (lane >> 2);
    float* dst = g_attn + (size_t)(b * T_ + r) * D_ + h * HD_ + mcol0;
#pragma unroll
    for (int jh = 0; jh < 8; jh++) {
        float2 v0 = make_float2(o[jh][0] * i0, o[jh][1] * i0);
        float2 v1 = make_float2(o[jh][2] * i1, o[jh][3] * i1);
        *reinterpret_cast<float2*>(dst + 8 * jh)          = v0;
        *reinterpret_cast<float2*>(dst + 8 * jh + 8 * D_) = v1;
    }
}

// ============================== Launch =====================================
extern "C" void kernel_launch(void* const* d_in, const int* in_sizes, int n_in,
                              void* d_out, int out_size) {
    const float* x     = (const float*)d_in[0];
    const float* W_qkv = (const float*)d_in[1];
    const float* b_qkv = (const float*)d_in[2];
    const float* W_out = (const float*)d_in[3];
    const float* b_out = (const float*)d_in[4];
    const unsigned char* pmask = (const unsigned char*)d_in[5];
    float* out = (float*)d_out;

    float* qkv_p = nullptr;
    float* attn_p = nullptr;
    __nv_bfloat16 *ahi, *alo, *bhi, *blo;
    cudaGetSymbolAddress((void**)&qkv_p, g_qkv);
    cudaGetSymbolAddress((void**)&attn_p, g_attn);
    cudaGetSymbolAddress((void**)&ahi, g_gahi);
    cudaGetSymbolAddress((void**)&alo, g_galo);
    cudaGetSymbolAddress((void**)&bhi, g_gbhi);
    cudaGetSymbolAddress((void**)&blo, g_gblo);

    cudaFuncSetAttribute(gemm_bf16_kernel,
                         cudaFuncAttributeMaxDynamicSharedMemorySize, (int)GEMM_SMEM);
    cudaFuncSetAttribute(attn_mma_kernel,
                         cudaFuncAttributeMaxDynamicSharedMemorySize, (int)SMEM_BYTES);

    // 1) split x and W_qkv; QKV = x @ W_qkv + b_qkv (tensor cores)
    split_kernel<<<(BT_ * D_ / 4) / 256, 256>>>(
        (const float4*)x, (uint32_t*)ahi, (uint32_t*)alo, BT_ * D_ / 4);
    split_kernel<<<(D_ * D3_ / 4) / 256, 256>>>(
        (const float4*)W_qkv, (uint32_t*)bhi, (uint32_t*)blo, D_ * D3_ / 4);
    gemm_bf16_kernel<<<dim3(D3_ / 128, BT_ / 128), 256, GEMM_SMEM>>>(
        ahi, alo, bhi, blo, b_qkv, qkv_p, BT_, D3_, D_);

    // 2) RoPE + bf16 hi/lo splits (q, k, v)
    rope_bf16_kernel<<<(B_ * H_ * T_ * 32) / 256, 256>>>();

    // 3) mma.sync flash attention -> g_attn (B,T,D)
    attn_mma_kernel<<<dim3(T_ / 128, B_ * H_), 256, SMEM_BYTES>>>(pmask);

    // 4) split attn and W_out; out = attn @ W_out + b_out (tensor cores)
    split_kernel<<<(BT_ * D_ / 4) / 256, 256>>>(
        (const float4*)attn_p, (uint32_t*)ahi, (uint32_t*)alo, BT_ * D_ / 4);
    split_kernel<<<(D_ * D_ / 4) / 256, 256>>>(
        (const float4*)W_out, (uint32_t*)bhi, (uint32_t*)blo, D_ * D_ / 4);
    gemm_bf16_kernel<<<dim3(D_ / 128, BT_ / 128), 256, GEMM_SMEM>>>(
        ahi, alo, bhi, blo, b_out, out, BT_, D_, D_);
}

// round 7
// speedup vs baseline: 3.2924x; 1.0244x over previous
#include <cuda_runtime.h>
#include <cuda_bf16.h>
#include <math.h>
#include <stdint.h>

constexpr int B_  = 2;
constexpr int T_  = 2048;
constexpr int D_  = 1024;
constexpr int H_  = 16;
constexpr int HD_ = 64;
constexpr int BT_ = B_ * T_;
constexpr int D3_ = 3 * D_;
constexpr int NT_ = T_ / 128;   // 16 kv tiles

// Scratch
__device__ __nv_bfloat16 g_qhi[B_ * H_ * T_ * HD_];
__device__ __nv_bfloat16 g_qlo[B_ * H_ * T_ * HD_];
__device__ __nv_bfloat16 g_khi[B_ * H_ * T_ * HD_];
__device__ __nv_bfloat16 g_klo[B_ * H_ * T_ * HD_];
__device__ __nv_bfloat16 g_vhi[B_ * H_ * T_ * HD_];
__device__ __nv_bfloat16 g_vlo[B_ * H_ * T_ * HD_];
// GEMM operand splits (A: x, then attention output; B: W_qkv, then W_out)
__device__ __nv_bfloat16 g_gahi[BT_ * D_];
__device__ __nv_bfloat16 g_galo[BT_ * D_];
__device__ __nv_bfloat16 g_gbhi[D_ * D3_];
__device__ __nv_bfloat16 g_gblo[D_ * D3_];

// ============================ PTX helpers ==================================
__device__ __forceinline__ uint32_t smem_u32(const void* p) {
    uint32_t a;
    asm("{ .reg .u64 t; cvta.to.shared.u64 t, %1; cvt.u32.u64 %0, t; }"
        : "=r"(a) : "l"(p));
    return a;
}
#define SWZ(o) ((uint32_t)(o) ^ ((((uint32_t)(o)) >> 3) & 0x70u))

__device__ __forceinline__ void cp16(uint32_t dst, const void* src) {
    asm volatile("cp.async.cg.shared.global [%0], [%1], 16;" :: "r"(dst), "l"(src) : "memory");
}
#define CP_COMMIT() asm volatile("cp.async.commit_group;" ::: "memory")
#define CP_WAIT0()  asm volatile("cp.async.wait_group 0;" ::: "memory")
#define CP_WAIT1()  asm volatile("cp.async.wait_group 1;" ::: "memory")

#define LDSM4(R, a) \
    asm volatile("ldmatrix.sync.aligned.m8n8.x4.shared.b16 {%0,%1,%2,%3}, [%4];" \
        : "=r"((R)[0]), "=r"((R)[1]), "=r"((R)[2]), "=r"((R)[3]) : "r"(a))
#define LDSM4T(R, a) \
    asm volatile("ldmatrix.sync.aligned.m8n8.x4.trans.shared.b16 {%0,%1,%2,%3}, [%4];" \
        : "=r"((R)[0]), "=r"((R)[1]), "=r"((R)[2]), "=r"((R)[3]) : "r"(a))

__device__ __forceinline__ void mma16816(float* c, const uint32_t* a,
                                         uint32_t b0, uint32_t b1) {
    asm volatile("mma.sync.aligned.m16n8k16.row.col.f32.bf16.bf16.f32 "
        "{%0,%1,%2,%3}, {%4,%5,%6,%7}, {%8,%9}, {%0,%1,%2,%3};"
        : "+f"(c[0]), "+f"(c[1]), "+f"(c[2]), "+f"(c[3])
        : "r"(a[0]), "r"(a[1]), "r"(a[2]), "r"(a[3]), "r"(b0), "r"(b1));
}

__device__ __forceinline__ uint32_t packbf2(float x, float y) {
    __nv_bfloat16 hx = __float2bfloat16(x);
    __nv_bfloat16 hy = __float2bfloat16(y);
    return (uint32_t)__bfloat16_as_ushort(hx)
         | ((uint32_t)__bfloat16_as_ushort(hy) << 16);
}

__device__ __forceinline__ void split_store(__nv_bfloat16* hi, __nv_bfloat16* lo,
                                            size_t i, float v) {
    __nv_bfloat16 h = __float2bfloat16(v);
    hi[i] = h;
    lo[i] = __float2bfloat16(v - __bfloat162float(h));
}

// ===================== elementwise hi/lo split =============================
__global__ void split_kernel(const float4* __restrict__ src,
                             uint32_t* __restrict__ hi,
                             uint32_t* __restrict__ lo, int n4) {
    int i = blockIdx.x * blockDim.x + threadIdx.x;
    if (i >= n4) return;
    float4 v = src[i];
    __nv_bfloat16 h0 = __float2bfloat16(v.x);
    __nv_bfloat16 h1 = __float2bfloat16(v.y);
    __nv_bfloat16 h2 = __float2bfloat16(v.z);
    __nv_bfloat16 h3 = __float2bfloat16(v.w);
    hi[2 * i]     = (uint32_t)__bfloat16_as_ushort(h0)
                  | ((uint32_t)__bfloat16_as_ushort(h1) << 16);
    hi[2 * i + 1] = (uint32_t)__bfloat16_as_ushort(h2)
                  | ((uint32_t)__bfloat16_as_ushort(h3) << 16);
    lo[2 * i]     = packbf2(v.x - __bfloat162float(h0), v.y - __bfloat162float(h1));
    lo[2 * i + 1] = packbf2(v.z - __bfloat162float(h2), v.w - __bfloat162float(h3));
}

// ================= split-bf16 tensor-core GEMM =============================
// C = (Ahi+Alo)(Bhi+Blo) + bias.  BM=128 BN=128 BK=64, 256 thr, warp m64n32.
// mode 0: write fp32 C.  mode 1: QKV epilogue — RoPE + hi/lo split in place.
constexpr uint32_t GA_HI = 0;
constexpr uint32_t GA_LO = 16384;
constexpr uint32_t GB_HI = 32768;
constexpr uint32_t GB_LO = 49152;
constexpr uint32_t GBUF  = 65536;
constexpr uint32_t GEMM_SMEM = 131072;
constexpr int CSTR = 132;   // staged C tile stride (floats)

__device__ __forceinline__ void gemm_load(
    uint32_t base, int tid, int rowBase, int colBase, int k0, int K, int N,
    const __nv_bfloat16* Ahi, const __nv_bfloat16* Alo,
    const __nv_bfloat16* Bhi, const __nv_bfloat16* Blo) {
#pragma unroll
    for (int c = tid; c < 1024; c += 256) {
        int row = c >> 3, off = c & 7;
        uint32_t sw = SWZ(row * 128 + off * 16);
        size_t g = (size_t)(rowBase + row) * K + k0 + off * 8;
        cp16(base + GA_HI + sw, Ahi + g);
        cp16(base + GA_LO + sw, Alo + g);
    }
#pragma unroll
    for (int c = tid; c < 1024; c += 256) {
        int half = c >> 9, cc = c & 511;
        int row = cc >> 3, off = cc & 7;
        uint32_t sw = (uint32_t)(half * 8192) + SWZ(row * 128 + off * 16);
        size_t g = (size_t)(k0 + row) * N + colBase + half * 64 + off * 8;
        cp16(base + GB_HI + sw, Bhi + g);
        cp16(base + GB_LO + sw, Blo + g);
    }
}

__global__ __launch_bounds__(256, 1)
void gemm_bf16_kernel(const __nv_bfloat16* __restrict__ Ahi,
                      const __nv_bfloat16* __restrict__ Alo,
                      const __nv_bfloat16* __restrict__ Bhi,
                      const __nv_bfloat16* __restrict__ Blo,
                      const float* __restrict__ bias,
                      float* __restrict__ C, int M, int N, int K, int mode) {
    extern __shared__ unsigned char smraw[];
    uint32_t smem = (smem_u32(smraw) + 1023u) & ~1023u;
    unsigned char* smbase = smraw + (smem - smem_u32(smraw));

    const int tid = threadIdx.x;
    const int warp = tid >> 5, lane = tid & 31;
    const int grp = lane >> 3, rIn = lane & 7;
    const int rowBase = blockIdx.y * 128, colBase = blockIdx.x * 128;
    const int wrow = (warp >> 2) * 64, wc = (warp & 3) * 32;
    const int halfsel = wc >> 6;          // RESTORED (R6 bug was dropping this)
    const int cb = (wc & 63) >> 3;        // RESTORED
    const int NIT = K / 64;

    const uint32_t aoff = (uint32_t)((wrow + rIn + (grp & 1) * 8) * 128 + (grp >> 1) * 16);
    const uint32_t boff = (uint32_t)(grp * 1024 + rIn * 128);

    float acc[4][4][4];
#pragma unroll
    for (int m = 0; m < 4; m++)
#pragma unroll
        for (int n = 0; n < 4; n++)
#pragma unroll
            for (int i = 0; i < 4; i++) acc[m][n][i] = 0.0f;

    gemm_load(smem, tid, rowBase, colBase, 0, K, N, Ahi, Alo, Bhi, Blo);
    CP_COMMIT();

    for (int it = 0; it < NIT; it++) {
        __syncthreads();
        if (it + 1 < NIT) {
            gemm_load(smem + ((it + 1) & 1) * GBUF, tid, rowBase, colBase,
                      (it + 1) * 64, K, N, Ahi, Alo, Bhi, Blo);
            CP_COMMIT();
            CP_WAIT1();
        } else {
            CP_WAIT0();
        }
        __syncthreads();

        const uint32_t base = smem + (uint32_t)(it & 1) * GBUF;
        const uint32_t Ah = base + GA_HI, Al = base + GA_LO;
        const uint32_t Bh = base + GB_HI + halfsel * 8192;
        const uint32_t Bl = base + GB_LO + halfsel * 8192;

#pragma unroll
        for (int kh = 0; kh < 2; kh++) {
            uint32_t bh[4][4], bl[4][4];
#pragma unroll
            for (int n = 0; n < 4; n++) {
                uint32_t o = boff + (uint32_t)(kh * 4096 + (cb + n) * 16);
                LDSM4T(bh[n], Bh + SWZ(o));
                LDSM4T(bl[n], Bl + SWZ(o));
            }
#pragma unroll
            for (int s = 0; s < 2; s++) {
                uint32_t ah[4][4], al[4][4];
#pragma unroll
                for (int m = 0; m < 4; m++) {
                    uint32_t o = aoff + (uint32_t)(m * 2048 + (kh * 2 + s) * 32);
                    LDSM4(ah[m], Ah + SWZ(o));
                    LDSM4(al[m], Al + SWZ(o));
                }
#pragma unroll
                for (int m = 0; m < 4; m++)
#pragma unroll
                    for (int n = 0; n < 4; n++) {
                        mma16816(acc[m][n], ah[m], bh[n][2 * s], bh[n][2 * s + 1]);
                        mma16816(acc[m][n], ah[m], bl[n][2 * s], bl[n][2 * s + 1]);
                        mma16816(acc[m][n], al[m], bh[n][2 * s], bh[n][2 * s + 1]);
                    }
            }
        }
    }

    if (mode == 0) {
        // direct fp32 output + bias
#pragma unroll
        for (int m = 0; m < 4; m++) {
            int r0 = rowBase + wrow + m * 16 + (lane >> 2);
#pragma unroll
            for (int n = 0; n < 4; n++) {
                int col = colBase + wc + n * 8 + 2 * (lane & 3);
                float bx = bias[col], by = bias[col + 1];
                float2 v0 = make_float2(acc[m][n][0] + bx, acc[m][n][1] + by);
                float2 v1 = make_float2(acc[m][n][2] + bx, acc[m][n][3] + by);
                *reinterpret_cast<float2*>(&C[(size_t)r0 * N + col])       = v0;
                *reinterpret_cast<float2*>(&C[(size_t)(r0 + 8) * N + col]) = v1;
            }
        }
        return;
    }

    // ---- mode 1: QKV epilogue (stage tile, then RoPE + hi/lo split) ----
    __syncthreads();                         // all warps done with smem buffers
    float* Csm = reinterpret_cast<float*>(smbase);
#pragma unroll
    for (int m = 0; m < 4; m++) {
        int r0 = wrow + m * 16 + (lane >> 2);
#pragma unroll
        for (int n = 0; n < 4; n++) {
            int col = wc + n * 8 + 2 * (lane & 3);
            float bx = bias[colBase + col], by = bias[colBase + col + 1];
            Csm[r0 * CSTR + col]           = acc[m][n][0] + bx;
            Csm[r0 * CSTR + col + 1]       = acc[m][n][1] + by;
            Csm[(r0 + 8) * CSTR + col]     = acc[m][n][2] + bx;
            Csm[(r0 + 8) * CSTR + col + 1] = acc[m][n][3] + by;
        }
    }
    __syncthreads();

    const int type = colBase >> 10;          // 0=q, 1=k, 2=v
    const int cb2  = colBase & 1023;
    const int h0   = cb2 >> 6;               // first of 2 heads in this tile
    const int bb   = rowBase >> 11;          // batch
    const int t0   = rowBase & 2047;         // first token row

    if (type < 2) {
        __nv_bfloat16* dhi = (type == 0) ? g_qhi : g_khi;
        __nv_bfloat16* dlo = (type == 0) ? g_qlo : g_klo;
        int d2 = tid & 63;                   // pair-column within 2 heads
        int lh = d2 >> 5, d = d2 & 31;
        float expo = (float)(2 * d) * (1.0f / (float)HD_);
        float inv  = 1.0f / powf(10000.0f, expo);
        size_t hbase = ((size_t)(bb * H_ + h0 + lh)) * T_ * HD_;
#pragma unroll 4
        for (int rr = tid >> 6; rr < 128; rr += 4) {
            int t = t0 + rr;
            float s, c;
            sincosf((float)t * inv, &s, &c);
            float v1 = Csm[rr * CSTR + lh * 64 + d];
            float v2 = Csm[rr * CSTR + lh * 64 + d + 32];
            size_t o = hbase + (size_t)t * HD_;
            split_store(dhi, dlo, o + d,      v1 * c - v2 * s);
            split_store(dhi, dlo, o + d + 32, v2 * c + v1 * s);
        }
    } else {
        int cc = tid & 127;
        int lh = cc >> 6, d = cc & 63;
        size_t hbase = ((size_t)(bb * H_ + h0 + lh)) * T_ * HD_;
#pragma unroll 4
        for (int rr = tid >> 7; rr < 128; rr += 2) {
            float v = Csm[rr * CSTR + cc];
            split_store(g_vhi, g_vlo, hbase + (size_t)(t0 + rr) * HD_ + d, v);
        }
    }
}

// ================= mma.sync flash attention (bf16 split) ===================
constexpr uint32_t SM_QHI = 0;
constexpr uint32_t SM_QLO = 16384;
constexpr uint32_t SM_KV  = 32768;                 // + buf*65536
constexpr uint32_t KV_KHI = 0, KV_KLO = 16384, KV_VHI = 32768, KV_VLO = 49152;
constexpr uint32_t SM_MASK = 163840;               // T_ bytes
constexpr uint32_t SMEM_BYTES = 165888 + 1024;

__device__ __forceinline__ void load_kv_tile(
    uint32_t smem, int buf, int k0, int tid,
    const __nv_bfloat16* gkh, const __nv_bfloat16* gkl,
    const __nv_bfloat16* gvh, const __nv_bfloat16* gvl) {
    uint32_t base = smem + SM_KV + (uint32_t)buf * 65536u;
#pragma unroll
    for (int c = tid; c < 1024; c += 256) {
        int row = c >> 3, off = c & 7;
        uint32_t sw = SWZ(row * 128 + off * 16);
        size_t g = (size_t)(k0 + row) * HD_ + off * 8;
        cp16(base + KV_KHI + sw, gkh + g);
        cp16(base + KV_KLO + sw, gkl + g);
        cp16(base + KV_VHI + sw, gvh + g);
        cp16(base + KV_VLO + sw, gvl + g);
    }
}

__global__ __launch_bounds__(256, 1)
void attn_mma_kernel(const unsigned char* __restrict__ mask) {
    extern __shared__ unsigned char smraw[];
    uint32_t smem = (smem_u32(smraw) + 1023u) & ~1023u;
    unsigned char* smbyte = smraw + (smem - smem_u32(smraw));

    const int tid  = threadIdx.x;
    const int warp = tid >> 5, lane = tid & 31;
    const int grp  = lane >> 3, rIn = lane & 7;
    const int bh = blockIdx.y, b = bh >> 4, h = bh & 15;
    const int q0 = blockIdx.x * 128;
    const int wrow = warp * 16;

    const size_t hb = (size_t)bh * T_ * HD_;
    const __nv_bfloat16* gqh = g_qhi + hb + (size_t)q0 * HD_;
    const __nv_bfloat16* gql = g_qlo + hb + (size_t)q0 * HD_;
    const __nv_bfloat16* gkh = g_khi + hb;
    const __nv_bfloat16* gkl = g_klo + hb;
    const __nv_bfloat16* gvh = g_vhi + hb;
    const __nv_bfloat16* gvl = g_vlo + hb;

#pragma unroll
    for (int c = tid; c < 1024; c += 256) {
        int row = c >> 3, off = c & 7;
        uint32_t sw = SWZ(row * 128 + off * 16);
        size_t g = (size_t)row * HD_ + off * 8;
        cp16(smem + SM_QHI + sw, gqh + g);
        cp16(smem + SM_QLO + sw, gql + g);
    }
    if (tid < 128) cp16(smem + SM_MASK + tid * 16, mask + b * T_ + tid * 16);
    load_kv_tile(smem, 0, 0, tid, gkh, gkl, gvh, gvl);
    CP_COMMIT();
    CP_WAIT0();
    __syncthreads();

    uint32_t qh[4][4], ql[4][4];
    const uint32_t qoff = (uint32_t)((wrow + rIn + (grp & 1) * 8) * 128 + (grp >> 1) * 16);
#pragma unroll
    for (int kk = 0; kk < 4; kk++) {
        LDSM4(qh[kk], smem + SM_QHI + SWZ(qoff + kk * 32));
        LDSM4(ql[kk], smem + SM_QLO + SWZ(qoff + kk * 32));
    }

    float o[8][4];
#pragma unroll
    for (int j = 0; j < 8; j++)
#pragma unroll
        for (int i = 0; i < 4; i++) o[j][i] = 0.0f;
    float ls0 = 0.0f, ls1 = 0.0f;

    const uint32_t kb = (uint32_t)(rIn * 128 + grp * 16);
    const uint32_t vb = (uint32_t)(grp * 1024 + rIn * 128);
    const int mcol0 = 2 * (lane & 3);

    for (int t = 0; t < NT_; t++) {
        const uint32_t kvb = smem + SM_KV + (uint32_t)(t & 1) * 65536u;

        __syncthreads();
        if (t + 1 < NT_) {
            load_kv_tile(smem, (t + 1) & 1, (t + 1) * 128, tid, gkh, gkl, gvh, gvl);
            CP_COMMIT();
            CP_WAIT1();
        } else {
            CP_WAIT0();
        }
        __syncthreads();

        float c[16][4];
#pragma unroll
        for (int j = 0; j < 16; j++)
#pragma unroll
            for (int i = 0; i < 4; i++) c[j][i] = 0.0f;

#pragma unroll
        for (int kp = 0; kp < 2; kp++) {
#pragma unroll
            for (int j = 0; j < 16; j++) {
                uint32_t kh[4], kl[4];
                uint32_t off = (uint32_t)(1024 * j + kp * 64) + kb;
                LDSM4(kh, kvb + KV_KHI + SWZ(off));
                LDSM4(kl, kvb + KV_KLO + SWZ(off));
                mma16816(c[j], qh[2 * kp],     kh[0], kh[1]);
                mma16816(c[j], qh[2 * kp],     kl[0], kl[1]);
                mma16816(c[j], ql[2 * kp],     kh[0], kh[1]);
                mma16816(c[j], qh[2 * kp + 1], kh[2], kh[3]);
                mma16816(c[j], qh[2 * kp + 1], kl[2], kl[3]);
                mma16816(c[j], ql[2 * kp + 1], kh[2], kh[3]);
            }
        }

        const unsigned char* mk = smbyte + SM_MASK + t * 128;
#pragma unroll
        for (int p = 0; p < 4; p++) {
            uint32_t ph[2][4], pl[2][4];
#pragma unroll
            for (int q2 = 0; q2 < 2; q2++) {
#pragma unroll
                for (int jj = 0; jj < 2; jj++) {
                    int j = 4 * p + 2 * q2 + jj;
                    int cg = 8 * j + mcol0;
                    bool m0 = mk[cg], m1 = mk[cg + 1];
                    float p0 = m0 ? 0.0f : __expf(c[j][0] * 0.125f);
                    float p1 = m1 ? 0.0f : __expf(c[j][1] * 0.125f);
                    float p2 = m0 ? 0.0f : __expf(c[j][2] * 0.125f);
                    float p3 = m1 ? 0.0f : __expf(c[j][3] * 0.125f);
                    ls0 += p0 + p1;
                    ls1 += p2 + p3;
                    __nv_bfloat16 h0 = __float2bfloat16(p0);
                    __nv_bfloat16 h1 = __float2bfloat16(p1);
                    __nv_bfloat16 h2 = __float2bfloat16(p2);
                    __nv_bfloat16 h3 = __float2bfloat16(p3);
                    ph[q2][2 * jj + 0] = (uint32_t)__bfloat16_as_ushort(h0)
                                       | ((uint32_t)__bfloat16_as_ushort(h1) << 16);
                    ph[q2][2 * jj + 1] = (uint32_t)__bfloat16_as_ushort(h2)
                                       | ((uint32_t)__bfloat16_as_ushort(h3) << 16);
                    pl[q2][2 * jj + 0] = packbf2(p0 - __bfloat162float(h0),
                                                 p1 - __bfloat162float(h1));
                    pl[q2][2 * jj + 1] = packbf2(p2 - __bfloat162float(h2),
                                                 p3 - __bfloat162float(h3));
                }
            }
#pragma unroll
            for (int jh = 0; jh < 8; jh++) {
                uint32_t vh[4], vl[4];
                uint32_t off = (uint32_t)(4096 * p + 16 * jh) + vb;
                LDSM4T(vh, kvb + KV_VHI + SWZ(off));
                LDSM4T(vl, kvb + KV_VLO + SWZ(off));
                mma16816(o[jh], ph[0], vh[0], vh[1]);
                mma16816(o[jh], ph[0], vl[0], vl[1]);
                mma16816(o[jh], pl[0], vh[0], vh[1]);
                mma16816(o[jh], ph[1], vh[2], vh[3]);
                mma16816(o[jh], ph[1], vl[2], vl[3]);
                mma16816(o[jh], pl[1], vh[2], vh[3]);
            }
        }
    }

    ls0 += __shfl_xor_sync(0xffffffffu, ls0, 1);
    ls0 += __shfl_xor_sync(0xffffffffu, ls0, 2);
    ls1 += __shfl_xor_sync(0xffffffffu, ls1, 1);
    ls1 += __shfl_xor_sync(0xffffffffu, ls1, 2);
    float i0 = 1.0f / ls0, i1 = 1.0f / ls1;

    // epilogue: write bf16 hi/lo pairs directly into out-proj A operand
    int r = q0 + wrow + (lane >> 2);
    size_t off0 = ((size_t)(b * T_ + r) * D_ + h * HD_ + mcol0) >> 1;  // u32 index
    uint32_t* ahi = reinterpret_cast<uint32_t*>(g_gahi);
    uint32_t* alo = reinterpret_cast<uint32_t*>(g_galo);
#pragma unroll
    for (int jh = 0; jh < 8; jh++) {
        float a0 = o[jh][0] * i0, a1 = o[jh][1] * i0;
        float b0 = o[jh][2] * i1, b1 = o[jh][3] * i1;
        __nv_bfloat16 ha0 = __float2bfloat16(a0);
        __nv_bfloat16 ha1 = __float2bfloat16(a1);
        __nv_bfloat16 hb0 = __float2bfloat16(b0);
        __nv_bfloat16 hb1 = __float2bfloat16(b1);
        size_t i_w = off0 + 4 * jh;
        ahi[i_w] = (uint32_t)__bfloat16_as_ushort(ha0)
                 | ((uint32_t)__bfloat16_as_ushort(ha1) << 16);
        alo[i_w] = packbf2(a0 - __bfloat162float(ha0), a1 - __bfloat162float(ha1));
        size_t i_w2 = i_w + 4 * D_;       // row r+8 (8*D_ elements = 4*D_ u32)
        ahi[i_w2] = (uint32_t)__bfloat16_as_ushort(hb0)
                  | ((uint32_t)__bfloat16_as_ushort(hb1) << 16);
        alo[i_w2] = packbf2(b0 - __bfloat162float(hb0), b1 - __bfloat162float(hb1));
    }
}

// ============================== Launch =====================================
extern "C" void kernel_launch(void* const* d_in, const int* in_sizes, int n_in,
                              void* d_out, int out_size) {
    const float* x     = (const float*)d_in[0];
    const float* W_qkv = (const float*)d_in[1];
    const float* b_qkv = (const float*)d_in[2];
    const float* W_out = (const float*)d_in[3];
    const float* b_out = (const float*)d_in[4];
    const unsigned char* pmask = (const unsigned char*)d_in[5];
    float* out = (float*)d_out;

    __nv_bfloat16 *ahi, *alo, *bhi, *blo;
    cudaGetSymbolAddress((void**)&ahi, g_gahi);
    cudaGetSymbolAddress((void**)&alo, g_galo);
    cudaGetSymbolAddress((void**)&bhi, g_gbhi);
    cudaGetSymbolAddress((void**)&blo, g_gblo);

    cudaFuncSetAttribute(gemm_bf16_kernel,
                         cudaFuncAttributeMaxDynamicSharedMemorySize, (int)GEMM_SMEM);
    cudaFuncSetAttribute(attn_mma_kernel,
                         cudaFuncAttributeMaxDynamicSharedMemorySize, (int)SMEM_BYTES);

    // 1) split x, W_qkv; fused QKV GEMM + bias + RoPE + hi/lo split
    split_kernel<<<(BT_ * D_ / 4) / 256, 256>>>(
        (const float4*)x, (uint32_t*)ahi, (uint32_t*)alo, BT_ * D_ / 4);
    split_kernel<<<(D_ * D3_ / 4) / 256, 256>>>(
        (const float4*)W_qkv, (uint32_t*)bhi, (uint32_t*)blo, D_ * D3_ / 4);
    gemm_bf16_kernel<<<dim3(D3_ / 128, BT_ / 128), 256, GEMM_SMEM>>>(
        ahi, alo, bhi, blo, b_qkv, nullptr, BT_, D3_, D_, 1);

    // 2) flash attention (writes out-proj A operand hi/lo directly)
    attn_mma_kernel<<<dim3(T_ / 128, B_ * H_), 256, SMEM_BYTES>>>(pmask);

    // 3) split W_out; out-proj GEMM + bias -> d_out
    split_kernel<<<(D_ * D_ / 4) / 256, 256>>>(
        (const float4*)W_out, (uint32_t*)bhi, (uint32_t*)blo, D_ * D_ / 4);
    gemm_bf16_kernel<<<dim3(D_ / 128, BT_ / 128), 256, GEMM_SMEM>>>(
        ahi, alo, bhi, blo, b_out, out, BT_, D_, D_, 0);
}

// round 8
// speedup vs baseline: 3.6489x; 1.1083x over previous
#include <cuda_runtime.h>
#include <cuda_bf16.h>
#include <cuda_fp16.h>
#include <math.h>
#include <stdint.h>

constexpr int B_  = 2;
constexpr int T_  = 2048;
constexpr int D_  = 1024;
constexpr int H_  = 16;
constexpr int HD_ = 64;
constexpr int BT_ = B_ * T_;
constexpr int D3_ = 3 * D_;
constexpr int NT_ = T_ / 128;   // 16 kv tiles

// Scratch
__device__ __nv_bfloat16 g_qhi[B_ * H_ * T_ * HD_];
__device__ __nv_bfloat16 g_qlo[B_ * H_ * T_ * HD_];
__device__ __nv_bfloat16 g_khi[B_ * H_ * T_ * HD_];
__device__ __nv_bfloat16 g_klo[B_ * H_ * T_ * HD_];
__device__ __half        g_vhi[B_ * H_ * T_ * HD_];   // fp16 V split
__device__ __half        g_vlo[B_ * H_ * T_ * HD_];
// GEMM operand splits (A: x, then attention output; B: W_qkv, then W_out)
__device__ __nv_bfloat16 g_gahi[BT_ * D_];
__device__ __nv_bfloat16 g_galo[BT_ * D_];
__device__ __nv_bfloat16 g_gbhi[D_ * D3_];
__device__ __nv_bfloat16 g_gblo[D_ * D3_];

// ============================ PTX helpers ==================================
__device__ __forceinline__ uint32_t smem_u32(const void* p) {
    uint32_t a;
    asm("{ .reg .u64 t; cvta.to.shared.u64 t, %1; cvt.u32.u64 %0, t; }"
        : "=r"(a) : "l"(p));
    return a;
}
#define SWZ(o) ((uint32_t)(o) ^ ((((uint32_t)(o)) >> 3) & 0x70u))

__device__ __forceinline__ void cp16(uint32_t dst, const void* src) {
    asm volatile("cp.async.cg.shared.global [%0], [%1], 16;" :: "r"(dst), "l"(src) : "memory");
}
#define CP_COMMIT() asm volatile("cp.async.commit_group;" ::: "memory")
#define CP_WAIT0()  asm volatile("cp.async.wait_group 0;" ::: "memory")
#define CP_WAIT1()  asm volatile("cp.async.wait_group 1;" ::: "memory")

#define LDSM4(R, a) \
    asm volatile("ldmatrix.sync.aligned.m8n8.x4.shared.b16 {%0,%1,%2,%3}, [%4];" \
        : "=r"((R)[0]), "=r"((R)[1]), "=r"((R)[2]), "=r"((R)[3]) : "r"(a))
#define LDSM4T(R, a) \
    asm volatile("ldmatrix.sync.aligned.m8n8.x4.trans.shared.b16 {%0,%1,%2,%3}, [%4];" \
        : "=r"((R)[0]), "=r"((R)[1]), "=r"((R)[2]), "=r"((R)[3]) : "r"(a))

__device__ __forceinline__ void mma16816(float* c, const uint32_t* a,
                                         uint32_t b0, uint32_t b1) {
    asm volatile("mma.sync.aligned.m16n8k16.row.col.f32.bf16.bf16.f32 "
        "{%0,%1,%2,%3}, {%4,%5,%6,%7}, {%8,%9}, {%0,%1,%2,%3};"
        : "+f"(c[0]), "+f"(c[1]), "+f"(c[2]), "+f"(c[3])
        : "r"(a[0]), "r"(a[1]), "r"(a[2]), "r"(a[3]), "r"(b0), "r"(b1));
}
__device__ __forceinline__ void mma16816h(float* c, const uint32_t* a,
                                          uint32_t b0, uint32_t b1) {
    asm volatile("mma.sync.aligned.m16n8k16.row.col.f32.f16.f16.f32 "
        "{%0,%1,%2,%3}, {%4,%5,%6,%7}, {%8,%9}, {%0,%1,%2,%3};"
        : "+f"(c[0]), "+f"(c[1]), "+f"(c[2]), "+f"(c[3])
        : "r"(a[0]), "r"(a[1]), "r"(a[2]), "r"(a[3]), "r"(b0), "r"(b1));
}

__device__ __forceinline__ uint32_t packbf2(float x, float y) {
    __nv_bfloat16 hx = __float2bfloat16(x);
    __nv_bfloat16 hy = __float2bfloat16(y);
    return (uint32_t)__bfloat16_as_ushort(hx)
         | ((uint32_t)__bfloat16_as_ushort(hy) << 16);
}
__device__ __forceinline__ uint32_t packh2(float x, float y) {
    __half2 h = __floats2half2_rn(x, y);
    return *reinterpret_cast<uint32_t*>(&h);
}

__device__ __forceinline__ void split_store(__nv_bfloat16* hi, __nv_bfloat16* lo,
                                            size_t i, float v) {
    __nv_bfloat16 h = __float2bfloat16(v);
    hi[i] = h;
    lo[i] = __float2bfloat16(v - __bfloat162float(h));
}
__device__ __forceinline__ void split_store_h(__half* hi, __half* lo,
                                              size_t i, float v) {
    __half h = __float2half_rn(v);
    hi[i] = h;
    lo[i] = __float2half_rn(v - __half2float(h));
}

// ===================== elementwise hi/lo split =============================
__global__ void split_kernel(const float4* __restrict__ src,
                             uint32_t* __restrict__ hi,
                             uint32_t* __restrict__ lo, int n4) {
    int i = blockIdx.x * blockDim.x + threadIdx.x;
    if (i >= n4) return;
    float4 v = src[i];
    __nv_bfloat16 h0 = __float2bfloat16(v.x);
    __nv_bfloat16 h1 = __float2bfloat16(v.y);
    __nv_bfloat16 h2 = __float2bfloat16(v.z);
    __nv_bfloat16 h3 = __float2bfloat16(v.w);
    hi[2 * i]     = (uint32_t)__bfloat16_as_ushort(h0)
                  | ((uint32_t)__bfloat16_as_ushort(h1) << 16);
    hi[2 * i + 1] = (uint32_t)__bfloat16_as_ushort(h2)
                  | ((uint32_t)__bfloat16_as_ushort(h3) << 16);
    lo[2 * i]     = packbf2(v.x - __bfloat162float(h0), v.y - __bfloat162float(h1));
    lo[2 * i + 1] = packbf2(v.z - __bfloat162float(h2), v.w - __bfloat162float(h3));
}

// ================= split-bf16 tensor-core GEMM =============================
// C = (Ahi+Alo)(Bhi+Blo) + bias.  BM=128 BN=128 BK=64, 256 thr, warp m64n32.
// mode 0: write fp32 C.  mode 1: QKV epilogue — RoPE + hi/lo split in place.
constexpr uint32_t GA_HI = 0;
constexpr uint32_t GA_LO = 16384;
constexpr uint32_t GB_HI = 32768;
constexpr uint32_t GB_LO = 49152;
constexpr uint32_t GBUF  = 65536;
constexpr uint32_t GEMM_SMEM = 131072;
constexpr int CSTR = 132;   // staged C tile stride (floats)

__device__ __forceinline__ void gemm_load(
    uint32_t base, int tid, int rowBase, int colBase, int k0, int K, int N,
    const __nv_bfloat16* Ahi, const __nv_bfloat16* Alo,
    const __nv_bfloat16* Bhi, const __nv_bfloat16* Blo) {
#pragma unroll
    for (int c = tid; c < 1024; c += 256) {
        int row = c >> 3, off = c & 7;
        uint32_t sw = SWZ(row * 128 + off * 16);
        size_t g = (size_t)(rowBase + row) * K + k0 + off * 8;
        cp16(base + GA_HI + sw, Ahi + g);
        cp16(base + GA_LO + sw, Alo + g);
    }
#pragma unroll
    for (int c = tid; c < 1024; c += 256) {
        int half = c >> 9, cc = c & 511;
        int row = cc >> 3, off = cc & 7;
        uint32_t sw = (uint32_t)(half * 8192) + SWZ(row * 128 + off * 16);
        size_t g = (size_t)(k0 + row) * N + colBase + half * 64 + off * 8;
        cp16(base + GB_HI + sw, Bhi + g);
        cp16(base + GB_LO + sw, Blo + g);
    }
}

__global__ __launch_bounds__(256, 1)
void gemm_bf16_kernel(const __nv_bfloat16* __restrict__ Ahi,
                      const __nv_bfloat16* __restrict__ Alo,
                      const __nv_bfloat16* __restrict__ Bhi,
                      const __nv_bfloat16* __restrict__ Blo,
                      const float* __restrict__ bias,
                      float* __restrict__ C, int M, int N, int K, int mode) {
    extern __shared__ unsigned char smraw[];
    uint32_t smem = (smem_u32(smraw) + 1023u) & ~1023u;
    unsigned char* smbase = smraw + (smem - smem_u32(smraw));

    const int tid = threadIdx.x;
    const int warp = tid >> 5, lane = tid & 31;
    const int grp = lane >> 3, rIn = lane & 7;
    const int rowBase = blockIdx.y * 128, colBase = blockIdx.x * 128;
    const int wrow = (warp >> 2) * 64, wc = (warp & 3) * 32;
    const int halfsel = wc >> 6;
    const int cb = (wc & 63) >> 3;
    const int NIT = K / 64;

    const uint32_t aoff = (uint32_t)((wrow + rIn + (grp & 1) * 8) * 128 + (grp >> 1) * 16);
    const uint32_t boff = (uint32_t)(grp * 1024 + rIn * 128);

    float acc[4][4][4];
#pragma unroll
    for (int m = 0; m < 4; m++)
#pragma unroll
        for (int n = 0; n < 4; n++)
#pragma unroll
            for (int i = 0; i < 4; i++) acc[m][n][i] = 0.0f;

    gemm_load(smem, tid, rowBase, colBase, 0, K, N, Ahi, Alo, Bhi, Blo);
    CP_COMMIT();

    for (int it = 0; it < NIT; it++) {
        __syncthreads();
        if (it + 1 < NIT) {
            gemm_load(smem + ((it + 1) & 1) * GBUF, tid, rowBase, colBase,
                      (it + 1) * 64, K, N, Ahi, Alo, Bhi, Blo);
            CP_COMMIT();
            CP_WAIT1();
        } else {
            CP_WAIT0();
        }
        __syncthreads();

        const uint32_t base = smem + (uint32_t)(it & 1) * GBUF;
        const uint32_t Ah = base + GA_HI, Al = base + GA_LO;
        const uint32_t Bh = base + GB_HI + halfsel * 8192;
        const uint32_t Bl = base + GB_LO + halfsel * 8192;

#pragma unroll
        for (int kh = 0; kh < 2; kh++) {
            uint32_t bh[4][4], bl[4][4];
#pragma unroll
            for (int n = 0; n < 4; n++) {
                uint32_t o = boff + (uint32_t)(kh * 4096 + (cb + n) * 16);
                LDSM4T(bh[n], Bh + SWZ(o));
                LDSM4T(bl[n], Bl + SWZ(o));
            }
#pragma unroll
            for (int s = 0; s < 2; s++) {
                uint32_t ah[4][4], al[4][4];
#pragma unroll
                for (int m = 0; m < 4; m++) {
                    uint32_t o = aoff + (uint32_t)(m * 2048 + (kh * 2 + s) * 32);
                    LDSM4(ah[m], Ah + SWZ(o));
                    LDSM4(al[m], Al + SWZ(o));
                }
#pragma unroll
                for (int m = 0; m < 4; m++)
#pragma unroll
                    for (int n = 0; n < 4; n++) {
                        mma16816(acc[m][n], ah[m], bh[n][2 * s], bh[n][2 * s + 1]);
                        mma16816(acc[m][n], ah[m], bl[n][2 * s], bl[n][2 * s + 1]);
                        mma16816(acc[m][n], al[m], bh[n][2 * s], bh[n][2 * s + 1]);
                    }
            }
        }
    }

    if (mode == 0) {
        // direct fp32 output + bias
#pragma unroll
        for (int m = 0; m < 4; m++) {
            int r0 = rowBase + wrow + m * 16 + (lane >> 2);
#pragma unroll
            for (int n = 0; n < 4; n++) {
                int col = colBase + wc + n * 8 + 2 * (lane & 3);
                float bx = bias[col], by = bias[col + 1];
                float2 v0 = make_float2(acc[m][n][0] + bx, acc[m][n][1] + by);
                float2 v1 = make_float2(acc[m][n][2] + bx, acc[m][n][3] + by);
                *reinterpret_cast<float2*>(&C[(size_t)r0 * N + col])       = v0;
                *reinterpret_cast<float2*>(&C[(size_t)(r0 + 8) * N + col]) = v1;
            }
        }
        return;
    }

    // ---- mode 1: QKV epilogue (stage tile, then RoPE + hi/lo split) ----
    __syncthreads();                         // all warps done with smem buffers
    float* Csm = reinterpret_cast<float*>(smbase);
#pragma unroll
    for (int m = 0; m < 4; m++) {
        int r0 = wrow + m * 16 + (lane >> 2);
#pragma unroll
        for (int n = 0; n < 4; n++) {
            int col = wc + n * 8 + 2 * (lane & 3);
            float bx = bias[colBase + col], by = bias[colBase + col + 1];
            Csm[r0 * CSTR + col]           = acc[m][n][0] + bx;
            Csm[r0 * CSTR + col + 1]       = acc[m][n][1] + by;
            Csm[(r0 + 8) * CSTR + col]     = acc[m][n][2] + bx;
            Csm[(r0 + 8) * CSTR + col + 1] = acc[m][n][3] + by;
        }
    }
    __syncthreads();

    const int type = colBase >> 10;          // 0=q, 1=k, 2=v
    const int cb2  = colBase & 1023;
    const int h0   = cb2 >> 6;               // first of 2 heads in this tile
    const int bb   = rowBase >> 11;          // batch
    const int t0   = rowBase & 2047;         // first token row

    if (type < 2) {
        __nv_bfloat16* dhi = (type == 0) ? g_qhi : g_khi;
        __nv_bfloat16* dlo = (type == 0) ? g_qlo : g_klo;
        int d2 = tid & 63;                   // pair-column within 2 heads
        int lh = d2 >> 5, d = d2 & 31;
        float expo = (float)(2 * d) * (1.0f / (float)HD_);
        float inv  = 1.0f / powf(10000.0f, expo);
        size_t hbase = ((size_t)(bb * H_ + h0 + lh)) * T_ * HD_;
#pragma unroll 4
        for (int rr = tid >> 6; rr < 128; rr += 4) {
            int t = t0 + rr;
            float s, c;
            sincosf((float)t * inv, &s, &c);
            float v1 = Csm[rr * CSTR + lh * 64 + d];
            float v2 = Csm[rr * CSTR + lh * 64 + d + 32];
            size_t o = hbase + (size_t)t * HD_;
            split_store(dhi, dlo, o + d,      v1 * c - v2 * s);
            split_store(dhi, dlo, o + d + 32, v2 * c + v1 * s);
        }
    } else {
        int cc = tid & 127;
        int lh = cc >> 6, d = cc & 63;
        size_t hbase = ((size_t)(bb * H_ + h0 + lh)) * T_ * HD_;
#pragma unroll 4
        for (int rr = tid >> 7; rr < 128; rr += 2) {
            float v = Csm[rr * CSTR + cc];
            split_store_h(g_vhi, g_vlo, hbase + (size_t)(t0 + rr) * HD_ + d, v);
        }
    }
}

// ================= mma.sync flash attention =================================
// S = split-bf16 (3 products); P·V = fp16-P x split-fp16-V (2 products)
constexpr uint32_t SM_QHI = 0;
constexpr uint32_t SM_QLO = 16384;
constexpr uint32_t SM_KV  = 32768;                 // + buf*65536
constexpr uint32_t KV_KHI = 0, KV_KLO = 16384, KV_VHI = 32768, KV_VLO = 49152;
constexpr uint32_t SM_MASK = 163840;               // T_ bytes
constexpr uint32_t SMEM_BYTES = 165888 + 1024;

__device__ __forceinline__ void load_kv_tile(
    uint32_t smem, int buf, int k0, int tid,
    const __nv_bfloat16* gkh, const __nv_bfloat16* gkl,
    const __half* gvh, const __half* gvl) {
    uint32_t base = smem + SM_KV + (uint32_t)buf * 65536u;
#pragma unroll
    for (int c = tid; c < 1024; c += 256) {
        int row = c >> 3, off = c & 7;
        uint32_t sw = SWZ(row * 128 + off * 16);
        size_t g = (size_t)(k0 + row) * HD_ + off * 8;
        cp16(base + KV_KHI + sw, gkh + g);
        cp16(base + KV_KLO + sw, gkl + g);
        cp16(base + KV_VHI + sw, gvh + g);
        cp16(base + KV_VLO + sw, gvl + g);
    }
}

__global__ __launch_bounds__(256, 1)
void attn_mma_kernel(const unsigned char* __restrict__ mask) {
    extern __shared__ unsigned char smraw[];
    uint32_t smem = (smem_u32(smraw) + 1023u) & ~1023u;
    unsigned char* smbyte = smraw + (smem - smem_u32(smraw));

    const int tid  = threadIdx.x;
    const int warp = tid >> 5, lane = tid & 31;
    const int grp  = lane >> 3, rIn = lane & 7;
    const int bh = blockIdx.y, b = bh >> 4, h = bh & 15;
    const int q0 = blockIdx.x * 128;
    const int wrow = warp * 16;

    const size_t hb = (size_t)bh * T_ * HD_;
    const __nv_bfloat16* gqh = g_qhi + hb + (size_t)q0 * HD_;
    const __nv_bfloat16* gql = g_qlo + hb + (size_t)q0 * HD_;
    const __nv_bfloat16* gkh = g_khi + hb;
    const __nv_bfloat16* gkl = g_klo + hb;
    const __half* gvh = g_vhi + hb;
    const __half* gvl = g_vlo + hb;

#pragma unroll
    for (int c = tid; c < 1024; c += 256) {
        int row = c >> 3, off = c & 7;
        uint32_t sw = SWZ(row * 128 + off * 16);
        size_t g = (size_t)row * HD_ + off * 8;
        cp16(smem + SM_QHI + sw, gqh + g);
        cp16(smem + SM_QLO + sw, gql + g);
    }
    if (tid < 128) cp16(smem + SM_MASK + tid * 16, mask + b * T_ + tid * 16);
    load_kv_tile(smem, 0, 0, tid, gkh, gkl, gvh, gvl);
    CP_COMMIT();
    CP_WAIT0();
    __syncthreads();

    uint32_t qh[4][4], ql[4][4];
    const uint32_t qoff = (uint32_t)((wrow + rIn + (grp & 1) * 8) * 128 + (grp >> 1) * 16);
#pragma unroll
    for (int kk = 0; kk < 4; kk++) {
        LDSM4(qh[kk], smem + SM_QHI + SWZ(qoff + kk * 32));
        LDSM4(ql[kk], smem + SM_QLO + SWZ(qoff + kk * 32));
    }

    float o[8][4];
#pragma unroll
    for (int j = 0; j < 8; j++)
#pragma unroll
        for (int i = 0; i < 4; i++) o[j][i] = 0.0f;
    float ls0 = 0.0f, ls1 = 0.0f;

    const uint32_t kb = (uint32_t)(rIn * 128 + grp * 16);
    const uint32_t vb = (uint32_t)(grp * 1024 + rIn * 128);
    const int mcol0 = 2 * (lane & 3);

    for (int t = 0; t < NT_; t++) {
        const uint32_t kvb = smem + SM_KV + (uint32_t)(t & 1) * 65536u;

        __syncthreads();
        if (t + 1 < NT_) {
            load_kv_tile(smem, (t + 1) & 1, (t + 1) * 128, tid, gkh, gkl, gvh, gvl);
            CP_COMMIT();
            CP_WAIT1();
        } else {
            CP_WAIT0();
        }
        __syncthreads();

        float c[16][4];
#pragma unroll
        for (int j = 0; j < 16; j++)
#pragma unroll
            for (int i = 0; i < 4; i++) c[j][i] = 0.0f;

#pragma unroll
        for (int kp = 0; kp < 2; kp++) {
#pragma unroll
            for (int j = 0; j < 16; j++) {
                uint32_t kh[4], kl[4];
                uint32_t off = (uint32_t)(1024 * j + kp * 64) + kb;
                LDSM4(kh, kvb + KV_KHI + SWZ(off));
                LDSM4(kl, kvb + KV_KLO + SWZ(off));
                mma16816(c[j], qh[2 * kp],     kh[0], kh[1]);
                mma16816(c[j], qh[2 * kp],     kl[0], kl[1]);
                mma16816(c[j], ql[2 * kp],     kh[0], kh[1]);
                mma16816(c[j], qh[2 * kp + 1], kh[2], kh[3]);
                mma16816(c[j], qh[2 * kp + 1], kl[2], kl[3]);
                mma16816(c[j], ql[2 * kp + 1], kh[2], kh[3]);
            }
        }

        // softmax: p = exp(s/8) as fp16 (single); PV = p*vhi + p*vlo
        const unsigned char* mk = smbyte + SM_MASK + t * 128;
#pragma unroll
        for (int p = 0; p < 4; p++) {
            uint32_t ph[2][4];
#pragma unroll
            for (int q2 = 0; q2 < 2; q2++) {
#pragma unroll
                for (int jj = 0; jj < 2; jj++) {
                    int j = 4 * p + 2 * q2 + jj;
                    int cg = 8 * j + mcol0;
                    bool m0 = mk[cg], m1 = mk[cg + 1];
                    float p0 = m0 ? 0.0f : __expf(c[j][0] * 0.125f);
                    float p1 = m1 ? 0.0f : __expf(c[j][1] * 0.125f);
                    float p2 = m0 ? 0.0f : __expf(c[j][2] * 0.125f);
                    float p3 = m1 ? 0.0f : __expf(c[j][3] * 0.125f);
                    ls0 += p0 + p1;
                    ls1 += p2 + p3;
                    ph[q2][2 * jj + 0] = packh2(p0, p1);
                    ph[q2][2 * jj + 1] = packh2(p2, p3);
                }
            }
#pragma unroll
            for (int jh = 0; jh < 8; jh++) {
                uint32_t vh[4], vl[4];
                uint32_t off = (uint32_t)(4096 * p + 16 * jh) + vb;
                LDSM4T(vh, kvb + KV_VHI + SWZ(off));
                LDSM4T(vl, kvb + KV_VLO + SWZ(off));
                mma16816h(o[jh], ph[0], vh[0], vh[1]);
                mma16816h(o[jh], ph[0], vl[0], vl[1]);
                mma16816h(o[jh], ph[1], vh[2], vh[3]);
                mma16816h(o[jh], ph[1], vl[2], vl[3]);
            }
        }
    }

    ls0 += __shfl_xor_sync(0xffffffffu, ls0, 1);
    ls0 += __shfl_xor_sync(0xffffffffu, ls0, 2);
    ls1 += __shfl_xor_sync(0xffffffffu, ls1, 1);
    ls1 += __shfl_xor_sync(0xffffffffu, ls1, 2);
    float i0 = 1.0f / ls0, i1 = 1.0f / ls1;

    // epilogue: write bf16 hi/lo pairs directly into out-proj A operand
    int r = q0 + wrow + (lane >> 2);
    size_t off0 = ((size_t)(b * T_ + r) * D_ + h * HD_ + mcol0) >> 1;  // u32 index
    uint32_t* ahi = reinterpret_cast<uint32_t*>(g_gahi);
    uint32_t* alo = reinterpret_cast<uint32_t*>(g_galo);
#pragma unroll
    for (int jh = 0; jh < 8; jh++) {
        float a0 = o[jh][0] * i0, a1 = o[jh][1] * i0;
        float b0 = o[jh][2] * i1, b1 = o[jh][3] * i1;
        __nv_bfloat16 ha0 = __float2bfloat16(a0);
        __nv_bfloat16 ha1 = __float2bfloat16(a1);
        __nv_bfloat16 hb0 = __float2bfloat16(b0);
        __nv_bfloat16 hb1 = __float2bfloat16(b1);
        size_t i_w = off0 + 4 * jh;
        ahi[i_w] = (uint32_t)__bfloat16_as_ushort(ha0)
                 | ((uint32_t)__bfloat16_as_ushort(ha1) << 16);
        alo[i_w] = packbf2(a0 - __bfloat162float(ha0), a1 - __bfloat162float(ha1));
        size_t i_w2 = i_w + 4 * D_;       // row r+8
        ahi[i_w2] = (uint32_t)__bfloat16_as_ushort(hb0)
                  | ((uint32_t)__bfloat16_as_ushort(hb1) << 16);
        alo[i_w2] = packbf2(b0 - __bfloat162float(hb0), b1 - __bfloat162float(hb1));
    }
}

// ============================== Launch =====================================
extern "C" void kernel_launch(void* const* d_in, const int* in_sizes, int n_in,
                              void* d_out, int out_size) {
    const float* x     = (const float*)d_in[0];
    const float* W_qkv = (const float*)d_in[1];
    const float* b_qkv = (const float*)d_in[2];
    const float* W_out = (const float*)d_in[3];
    const float* b_out = (const float*)d_in[4];
    const unsigned char* pmask = (const unsigned char*)d_in[5];
    float* out = (float*)d_out;

    __nv_bfloat16 *ahi, *alo, *bhi, *blo;
    cudaGetSymbolAddress((void**)&ahi, g_gahi);
    cudaGetSymbolAddress((void**)&alo, g_galo);
    cudaGetSymbolAddress((void**)&bhi, g_gbhi);
    cudaGetSymbolAddress((void**)&blo, g_gblo);

    cudaFuncSetAttribute(gemm_bf16_kernel,
                         cudaFuncAttributeMaxDynamicSharedMemorySize, (int)GEMM_SMEM);
    cudaFuncSetAttribute(attn_mma_kernel,
                         cudaFuncAttributeMaxDynamicSharedMemorySize, (int)SMEM_BYTES);

    // 1) split x, W_qkv; fused QKV GEMM + bias + RoPE + hi/lo split
    split_kernel<<<(BT_ * D_ / 4) / 256, 256>>>(
        (const float4*)x, (uint32_t*)ahi, (uint32_t*)alo, BT_ * D_ / 4);
    split_kernel<<<(D_ * D3_ / 4) / 256, 256>>>(
        (const float4*)W_qkv, (uint32_t*)bhi, (uint32_t*)blo, D_ * D3_ / 4);
    gemm_bf16_kernel<<<dim3(D3_ / 128, BT_ / 128), 256, GEMM_SMEM>>>(
        ahi, alo, bhi, blo, b_qkv, nullptr, BT_, D3_, D_, 1);

    // 2) flash attention (writes out-proj A operand hi/lo directly)
    attn_mma_kernel<<<dim3(T_ / 128, B_ * H_), 256, SMEM_BYTES>>>(pmask);

    // 3) split W_out; out-proj GEMM + bias -> d_out
    split_kernel<<<(D_ * D_ / 4) / 256, 256>>>(
        (const float4*)W_out, (uint32_t*)bhi, (uint32_t*)blo, D_ * D_ / 4);
    gemm_bf16_kernel<<<dim3(D_ / 128, BT_ / 128), 256, GEMM_SMEM>>>(
        ahi, alo, bhi, blo, b_out, out, BT_, D_, D_, 0);
}